// round 1
// baseline (speedup 1.0000x reference)
#include <cuda_runtime.h>
#include <cuda_bf16.h>
#include <cstdint>
#include <math.h>

#define B_ 4
#define H_ 8
#define T_ 8192
#define D_ 64
#define C_ 64
#define W_ 128
#define BH_ (B_*H_)

// ---------------- scratch (static device globals; no runtime allocation) ----------------
__device__ float g_dists[(size_t)BH_ * C_ * T_];   // [bh][c][t]  64 MB
__device__ int   g_idx[BH_ * C_ * W_];             // sorted indices per cluster
__device__ float g_den[BH_ * T_];                  // scatter counts
__device__ float g_loss;

// ---------------- zero den/loss ----------------
__global__ void k_zero() {
    int i = blockIdx.x * blockDim.x + threadIdx.x;
    if (i < BH_ * T_) g_den[i] = 0.f;
    if (i == 0) g_loss = 0.f;
}

// ---------------- dists = l2norm(qk) . means   [bh][c][t] ----------------
__global__ void __launch_bounds__(256) k_dists(const float* __restrict__ qk,
                                               const float* __restrict__ means) {
    __shared__ float sQ[64 * 65];
    __shared__ float sM[64 * 65];
    __shared__ float sInv[64];
    int bh = blockIdx.y;
    int h = bh & (H_ - 1);
    int t0 = blockIdx.x * 64;
    const float* qp = qk + ((size_t)bh * T_ + t0) * D_;
    const float* mp = means + (size_t)h * C_ * D_;
    int tid = threadIdx.x;

    for (int i = tid; i < 64 * 16; i += 256) {
        int r = i >> 4, c4 = (i & 15) << 2;
        float4 a = *(const float4*)(qp + r * D_ + c4);
        sQ[r * 65 + c4 + 0] = a.x; sQ[r * 65 + c4 + 1] = a.y;
        sQ[r * 65 + c4 + 2] = a.z; sQ[r * 65 + c4 + 3] = a.w;
        float4 m = *(const float4*)(mp + r * D_ + c4);
        sM[r * 65 + c4 + 0] = m.x; sM[r * 65 + c4 + 1] = m.y;
        sM[r * 65 + c4 + 2] = m.z; sM[r * 65 + c4 + 3] = m.w;
    }
    __syncthreads();
    if (tid < 64) {
        float s = 0.f;
        #pragma unroll
        for (int k = 0; k < 64; k++) { float x = sQ[tid * 65 + k]; s += x * x; }
        sInv[tid] = 1.f / fmaxf(sqrtf(s), 1e-12f);
    }
    __syncthreads();

    int ty = tid >> 4, tx = tid & 15;
    float acc[4][4];
    #pragma unroll
    for (int u = 0; u < 4; u++)
        #pragma unroll
        for (int w = 0; w < 4; w++) acc[u][w] = 0.f;

    for (int k = 0; k < 64; k++) {
        float a[4], b[4];
        #pragma unroll
        for (int u = 0; u < 4; u++) a[u] = sQ[(ty * 4 + u) * 65 + k];
        #pragma unroll
        for (int w = 0; w < 4; w++) b[w] = sM[(tx * 4 + w) * 65 + k];
        #pragma unroll
        for (int u = 0; u < 4; u++)
            #pragma unroll
            for (int w = 0; w < 4; w++) acc[u][w] += a[u] * b[w];
    }
    __syncthreads();
    // stage as [c][token] for coalesced global writes
    #pragma unroll
    for (int u = 0; u < 4; u++)
        #pragma unroll
        for (int w = 0; w < 4; w++)
            sQ[(tx * 4 + w) * 65 + (ty * 4 + u)] = acc[u][w] * sInv[ty * 4 + u];
    __syncthreads();
    float* dst = &g_dists[((size_t)bh * C_) * T_ + t0];
    for (int i = tid; i < 4096; i += 256) {
        int c = i >> 6, r = i & 63;
        dst[(size_t)c * T_ + r] = sQ[c * 65 + r];
    }
}

// ---------------- commitment loss: sum over tokens of (2 - 2*max_c dist) ----------------
__global__ void k_lossk() {
    int bh = blockIdx.y;
    int t = blockIdx.x * 256 + threadIdx.x;
    const float* dp = &g_dists[(size_t)bh * C_ * T_ + t];
    float m = -1e30f;
    #pragma unroll 8
    for (int c = 0; c < C_; c++) m = fmaxf(m, dp[(size_t)c * T_]);
    float v = 2.f - 2.f * m;
    // block reduce
    #pragma unroll
    for (int off = 16; off > 0; off >>= 1) v += __shfl_down_sync(0xFFFFFFFFu, v, off);
    __shared__ float ws[8];
    int lane = threadIdx.x & 31, wid = threadIdx.x >> 5;
    if (lane == 0) ws[wid] = v;
    __syncthreads();
    if (threadIdx.x == 0) {
        float s = 0.f;
        #pragma unroll
        for (int i = 0; i < 8; i++) s += ws[i];
        atomicAdd(&g_loss, s);
    }
}

// ---------------- exact top-128 per (bh,c) row + ascending index sort ----------------
__global__ void __launch_bounds__(256) k_topk() {
    int row = blockIdx.x;                       // bh*C + c
    const float* dp = g_dists + (size_t)row * T_;
    int tid = threadIdx.x;
    unsigned key[32];
    #pragma unroll
    for (int k = 0; k < 32; k++) {
        unsigned u = __float_as_uint(dp[tid + (k << 8)]);
        key[k] = (u & 0x80000000u) ? ~u : (u | 0x80000000u);   // order-preserving map
    }
    __shared__ int hist[256];
    __shared__ int sSel, sKth, sCnt, sMin;
    __shared__ int sIdx[128];

    unsigned prefix = 0, pmask = 0;
    int kth = 128;
    for (int shift = 24; shift >= 0; shift -= 8) {
        hist[tid] = 0;
        __syncthreads();
        #pragma unroll
        for (int k = 0; k < 32; k++)
            if ((key[k] & pmask) == prefix)
                atomicAdd(&hist[(key[k] >> shift) & 255], 1);
        __syncthreads();
        if (tid == 0) {
            int cum = 0, b = 255;
            for (; b >= 0; --b) { cum += hist[b]; if (cum >= kth) break; }
            if (b < 0) b = 0;
            sSel = b;
            sKth = kth - (cum - hist[b]);
        }
        __syncthreads();
        prefix |= ((unsigned)sSel) << shift;
        pmask  |= 0xFFu << shift;
        kth = sKth;
        __syncthreads();
    }
    // prefix == key value of the 128th largest
    if (tid == 0) sCnt = 0;
    __syncthreads();
    #pragma unroll
    for (int k = 0; k < 32; k++)
        if (key[k] > prefix) {
            int p = atomicAdd(&sCnt, 1);
            sIdx[p] = tid + (k << 8);
        }
    __syncthreads();
    int ngt = sCnt;
    int need = 128 - ngt;       // >=1; ties at threshold take smallest indices (matches lax.top_k)
    int last = -1;
    for (int s = 0; s < need; s++) {
        if (tid == 0) sMin = 0x7FFFFFFF;
        __syncthreads();
        #pragma unroll
        for (int k = 0; k < 32; k++) {
            if (key[k] == prefix) {
                int id2 = tid + (k << 8);
                if (id2 > last) atomicMin(&sMin, id2);
            }
        }
        __syncthreads();
        int m = sMin;
        if (tid == 0) sIdx[ngt + s] = m;
        last = m;
        __syncthreads();
    }
    // bitonic sort ascending, 128 elems
    for (int sz = 2; sz <= 128; sz <<= 1) {
        for (int st = sz >> 1; st > 0; st >>= 1) {
            if (tid < 128) {
                int i = tid, ixj = i ^ st;
                if (ixj > i) {
                    int a = sIdx[i], b2 = sIdx[ixj];
                    bool up = ((i & sz) == 0);
                    if ((a > b2) == up) { sIdx[i] = b2; sIdx[ixj] = a; }
                }
            }
            __syncthreads();
        }
    }
    if (tid < 128) g_idx[row * W_ + tid] = sIdx[tid];
}

// ---------------- fused gather + local attention + scatter ----------------
// smem: sQT[64][132] (k-major Q), sRT[64][132] (k-major rel_w), sV[128][68],
//       sD[128][129] (dots/attn), sInv[128], sIdx[128]
#define SM_QT   (64 * 132)
#define SM_RT   (64 * 132)
#define SM_V    (128 * 68)
#define SM_D    (128 * 129)
#define SMEM_ATTN_BYTES ((SM_QT + SM_RT + SM_V + SM_D + 128) * 4 + 128 * 4)

__global__ void __launch_bounds__(256) k_attn(const float* __restrict__ qk,
                                              const float* __restrict__ vv,
                                              const float* __restrict__ relw,
                                              float* __restrict__ outNum) {
    extern __shared__ float sm[];
    float* sQT  = sm;
    float* sRT  = sQT + SM_QT;
    float* sV   = sRT + SM_RT;
    float* sD   = sV + SM_V;
    float* sInv = sD + SM_D;
    int*   sIdx = (int*)(sInv + 128);

    int bhc = blockIdx.x;
    int bh = bhc >> 6;
    int h = bh & (H_ - 1);
    int tid = threadIdx.x;

    if (tid < 128) sIdx[tid] = g_idx[bhc * W_ + tid];
    __syncthreads();

    // gather qk rows (k-major), v rows (row-major), rel_w rows (k-major)
    for (int i = tid; i < 128 * 16; i += 256) {
        int r = i >> 4, c4 = (i & 15) << 2;
        int tok = sIdx[r];
        float4 q4 = *(const float4*)(qk + ((size_t)bh * T_ + tok) * D_ + c4);
        sQT[(c4 + 0) * 132 + r] = q4.x; sQT[(c4 + 1) * 132 + r] = q4.y;
        sQT[(c4 + 2) * 132 + r] = q4.z; sQT[(c4 + 3) * 132 + r] = q4.w;
        float4 v4 = *(const float4*)(vv + ((size_t)bh * T_ + tok) * D_ + c4);
        float* vd = sV + r * 68 + c4;
        vd[0] = v4.x; vd[1] = v4.y; vd[2] = v4.z; vd[3] = v4.w;
        float4 r4 = *(const float4*)(relw + ((size_t)r * H_ + h) * D_ + c4);
        sRT[(c4 + 0) * 132 + r] = r4.x; sRT[(c4 + 1) * 132 + r] = r4.y;
        sRT[(c4 + 2) * 132 + r] = r4.z; sRT[(c4 + 3) * 132 + r] = r4.w;
    }
    __syncthreads();

    if (tid < 128) {
        float s = 0.f;
        #pragma unroll
        for (int k = 0; k < 64; k++) { float x = sQT[k * 132 + tid]; s += x * x; }
        sInv[tid] = 1.f / fmaxf(sqrtf(s), 1e-12f);
    }
    __syncthreads();

    int ty = tid >> 4, tx = tid & 15;
    const float scale = 0.125f;

    // ---- GEMM1: dots[i][j] = scale * inv_j * (q_i . q_j) ----
    float acc[8][8];
    #pragma unroll
    for (int u = 0; u < 8; u++)
        #pragma unroll
        for (int w = 0; w < 8; w++) acc[u][w] = 0.f;
    for (int k = 0; k < 64; k++) {
        const float4* rk = (const float4*)(sQT + k * 132);
        float4 a0 = rk[ty * 2], a1 = rk[ty * 2 + 1];
        float4 b0 = rk[tx * 2], b1 = rk[tx * 2 + 1];
        float a[8] = {a0.x, a0.y, a0.z, a0.w, a1.x, a1.y, a1.z, a1.w};
        float b[8] = {b0.x, b0.y, b0.z, b0.w, b1.x, b1.y, b1.z, b1.w};
        #pragma unroll
        for (int u = 0; u < 8; u++)
            #pragma unroll
            for (int w = 0; w < 8; w++) acc[u][w] += a[u] * b[w];
    }
    {
        float invj[8];
        #pragma unroll
        for (int w = 0; w < 8; w++) invj[w] = sInv[tx * 8 + w] * scale;
        #pragma unroll
        for (int u = 0; u < 8; u++)
            #pragma unroll
            for (int w = 0; w < 8; w++)
                sD[(ty * 8 + u) * 129 + tx * 8 + w] = acc[u][w] * invj[w];
    }
    __syncthreads();

    // ---- GEMM2: R[i][jj] = scale * (q_i . rw_jj); add shifted: dots[i][i+jj-127] += R ----
    #pragma unroll
    for (int u = 0; u < 8; u++)
        #pragma unroll
        for (int w = 0; w < 8; w++) acc[u][w] = 0.f;
    for (int k = 0; k < 64; k++) {
        const float4* rk = (const float4*)(sQT + k * 132);
        float4 a0 = rk[ty * 2], a1 = rk[ty * 2 + 1];
        const float4* rr = (const float4*)(sRT + k * 132);
        float4 b0 = rr[tx * 2], b1 = rr[tx * 2 + 1];
        float a[8] = {a0.x, a0.y, a0.z, a0.w, a1.x, a1.y, a1.z, a1.w};
        float b[8] = {b0.x, b0.y, b0.z, b0.w, b1.x, b1.y, b1.z, b1.w};
        #pragma unroll
        for (int u = 0; u < 8; u++)
            #pragma unroll
            for (int w = 0; w < 8; w++) acc[u][w] += a[u] * b[w];
    }
    #pragma unroll
    for (int u = 0; u < 8; u++) {
        int i = ty * 8 + u;
        #pragma unroll
        for (int w = 0; w < 8; w++) {
            int j = i + (tx * 8 + w) - 127;
            if (j >= 0) sD[i * 129 + j] += acc[u][w] * scale;
        }
    }
    __syncthreads();

    if (tid < 128) sD[tid * 129 + tid] = -50000.0f;
    __syncthreads();

    // ---- softmax rows ----
    if (tid < 128) {
        float m = -1e30f;
        #pragma unroll 8
        for (int j = 0; j < 128; j++) m = fmaxf(m, sD[tid * 129 + j]);
        float s = 0.f;
        #pragma unroll 4
        for (int j = 0; j < 128; j++) {
            float e = expf(sD[tid * 129 + j] - m);
            sD[tid * 129 + j] = e;
            s += e;
        }
        float inv = 1.f / s;
        #pragma unroll 8
        for (int j = 0; j < 128; j++) sD[tid * 129 + j] *= inv;
    }
    __syncthreads();

    // ---- AV: bo[i][d] = sum_j attn[i][j] * v[j][d] ----
    float av[8][4];
    #pragma unroll
    for (int u = 0; u < 8; u++)
        #pragma unroll
        for (int w = 0; w < 4; w++) av[u][w] = 0.f;
    for (int j = 0; j < 128; j++) {
        float4 bv = *(const float4*)(sV + j * 68 + tx * 4);
        #pragma unroll
        for (int u = 0; u < 8; u++) {
            float a = sD[(ty * 8 + u) * 129 + j];
            av[u][0] += a * bv.x; av[u][1] += a * bv.y;
            av[u][2] += a * bv.z; av[u][3] += a * bv.w;
        }
    }

    // ---- scatter (vector fp32 red) ----
    #pragma unroll
    for (int u = 0; u < 8; u++) {
        int tok = sIdx[ty * 8 + u];
        float4 val = make_float4(av[u][0], av[u][1], av[u][2], av[u][3]);
        atomicAdd((float4*)(outNum + ((size_t)bh * T_ + tok) * D_ + tx * 4), val);
    }
    if (tx == 0) {
        #pragma unroll
        for (int u = 0; u < 8; u++)
            atomicAdd(&g_den[(size_t)bh * T_ + sIdx[ty * 8 + u]], 1.0f);
    }
}

// ---------------- normalize out = num/(den+eps); write loss ----------------
__global__ void k_norm(float* __restrict__ out, int has_loss) {
    size_t gid = (size_t)blockIdx.x * 256 + threadIdx.x;   // one float4 per thread
    float den = g_den[gid >> 4];
    float s = 1.f / (den + 1e-5f);
    float4* o4 = (float4*)out;
    float4 v = o4[gid];
    v.x *= s; v.y *= s; v.z *= s; v.w *= s;
    o4[gid] = v;
    if (gid == 0 && has_loss)
        out[(size_t)BH_ * T_ * D_] = g_loss * (0.0001f / (float)((size_t)BH_ * T_ * D_));
}

// ---------------- launch ----------------
extern "C" void kernel_launch(void* const* d_in, const int* in_sizes, int n_in,
                              void* d_out, int out_size) {
    const float* qk    = (const float*)d_in[0];
    const float* v     = (const float*)d_in[1];
    const float* means = (const float*)d_in[2];
    const float* relw  = (const float*)d_in[3];
    // defensive: distinguish means (32768) vs rel_w (65536) by size if swapped
    if (n_in >= 4 && in_sizes[2] == W_ * H_ * D_ && in_sizes[3] == H_ * C_ * D_) {
        relw  = (const float*)d_in[2];
        means = (const float*)d_in[3];
    }
    float* out = (float*)d_out;

    cudaMemsetAsync(d_out, 0, (size_t)out_size * sizeof(float), 0);
    k_zero<<<(BH_ * T_ + 255) / 256, 256>>>();

    dim3 g1(T_ / 64, BH_);
    k_dists<<<g1, 256>>>(qk, means);

    dim3 gl(T_ / 256, BH_);
    k_lossk<<<gl, 256>>>();

    k_topk<<<BH_ * C_, 256>>>();

    cudaFuncSetAttribute(k_attn, cudaFuncAttributeMaxDynamicSharedMemorySize, SMEM_ATTN_BYTES);
    k_attn<<<BH_ * C_, 256, SMEM_ATTN_BYTES>>>(qk, v, relw, out);

    int nf4 = BH_ * T_ * D_ / 4;
    k_norm<<<nf4 / 256, 256>>>(out, out_size > BH_ * T_ * D_ ? 1 : 0);
}

// round 4
// speedup vs baseline: 1.4526x; 1.4526x over previous
#include <cuda_runtime.h>
#include <cuda_bf16.h>
#include <cstdint>
#include <math.h>

#define B_ 4
#define H_ 8
#define T_ 8192
#define D_ 64
#define C_ 64
#define W_ 128
#define BH_ (B_*H_)

// ---------------- scratch ----------------
__device__ float g_dists[(size_t)BH_ * C_ * T_];   // [bh][c][t]
__device__ int   g_idx[BH_ * C_ * W_];
__device__ float g_den[BH_ * T_];
__device__ float g_loss;

__device__ __forceinline__ uint32_t packbf(__nv_bfloat16 a, __nv_bfloat16 b) {
    return ((uint32_t)__bfloat16_as_ushort(b) << 16) | (uint32_t)__bfloat16_as_ushort(a);
}
__device__ __forceinline__ void mma_bf16(float (&c)[4], const uint32_t (&a)[4],
                                         uint32_t b0, uint32_t b1) {
    asm volatile("mma.sync.aligned.m16n8k16.row.col.f32.bf16.bf16.f32 "
        "{%0,%1,%2,%3}, {%4,%5,%6,%7}, {%8,%9}, {%0,%1,%2,%3};"
        : "+f"(c[0]), "+f"(c[1]), "+f"(c[2]), "+f"(c[3])
        : "r"(a[0]), "r"(a[1]), "r"(a[2]), "r"(a[3]), "r"(b0), "r"(b1));
}

// ---------------- zero den/loss ----------------
__global__ void k_zero() {
    int i = blockIdx.x * blockDim.x + threadIdx.x;
    if (i < BH_ * T_) g_den[i] = 0.f;
    if (i == 0) g_loss = 0.f;
}

// ---------------- dists = l2norm(qk) . means, fused commitment loss ----------------
__global__ void __launch_bounds__(256) k_dists(const float* __restrict__ qk,
                                               const float* __restrict__ means) {
    __shared__ float sQ[64 * 65];
    __shared__ float sM[64 * 65];
    __shared__ float sInv[64];
    int bh = blockIdx.y;
    int h = bh & (H_ - 1);
    int t0 = blockIdx.x * 64;
    const float* qp = qk + ((size_t)bh * T_ + t0) * D_;
    const float* mp = means + (size_t)h * C_ * D_;
    int tid = threadIdx.x;

    for (int i = tid; i < 64 * 16; i += 256) {
        int r = i >> 4, c4 = (i & 15) << 2;
        float4 a = *(const float4*)(qp + r * D_ + c4);
        sQ[r * 65 + c4 + 0] = a.x; sQ[r * 65 + c4 + 1] = a.y;
        sQ[r * 65 + c4 + 2] = a.z; sQ[r * 65 + c4 + 3] = a.w;
        float4 m = *(const float4*)(mp + r * D_ + c4);
        sM[r * 65 + c4 + 0] = m.x; sM[r * 65 + c4 + 1] = m.y;
        sM[r * 65 + c4 + 2] = m.z; sM[r * 65 + c4 + 3] = m.w;
    }
    __syncthreads();
    if (tid < 64) {
        float s = 0.f;
        #pragma unroll
        for (int k = 0; k < 64; k++) { float x = sQ[tid * 65 + k]; s += x * x; }
        sInv[tid] = 1.f / fmaxf(sqrtf(s), 1e-12f);
    }
    __syncthreads();

    int ty = tid >> 4, tx = tid & 15;
    float acc[4][4];
    #pragma unroll
    for (int u = 0; u < 4; u++)
        #pragma unroll
        for (int w = 0; w < 4; w++) acc[u][w] = 0.f;

    for (int k = 0; k < 64; k++) {
        float a[4], b[4];
        #pragma unroll
        for (int u = 0; u < 4; u++) a[u] = sQ[(ty * 4 + u) * 65 + k];
        #pragma unroll
        for (int w = 0; w < 4; w++) b[w] = sM[(tx * 4 + w) * 65 + k];
        #pragma unroll
        for (int u = 0; u < 4; u++)
            #pragma unroll
            for (int w = 0; w < 4; w++) acc[u][w] += a[u] * b[w];
    }
    __syncthreads();
    #pragma unroll
    for (int u = 0; u < 4; u++)
        #pragma unroll
        for (int w = 0; w < 4; w++)
            sQ[(tx * 4 + w) * 65 + (ty * 4 + u)] = acc[u][w] * sInv[ty * 4 + u];
    __syncthreads();
    float* dst = &g_dists[((size_t)bh * C_) * T_ + t0];
    for (int i = tid; i < 4096; i += 256) {
        int c = i >> 6, r = i & 63;
        dst[(size_t)c * T_ + r] = sQ[c * 65 + r];
    }
    // fused loss: per-token 2 - 2*max_c dist
    if (tid < 64) {
        float m = -1e30f;
        #pragma unroll 8
        for (int c = 0; c < 64; c++) m = fmaxf(m, sQ[c * 65 + tid]);
        float v = 2.f - 2.f * m;
        #pragma unroll
        for (int off = 16; off > 0; off >>= 1) v += __shfl_down_sync(0xFFFFFFFFu, v, off);
        if ((tid & 31) == 0) atomicAdd(&g_loss, v);
    }
}

// ---------------- exact top-128 per (bh,c) row + ascending index sort ----------------
__global__ void __launch_bounds__(512) k_topk() {
    int row = blockIdx.x;
    const float* dp = g_dists + (size_t)row * T_;
    int tid = threadIdx.x;
    unsigned key[16];
    #pragma unroll
    for (int k = 0; k < 16; k++) {
        unsigned u = __float_as_uint(dp[tid + (k << 9)]);
        key[k] = (u & 0x80000000u) ? ~u : (u | 0x80000000u);
    }
    __shared__ int hist[256];
    __shared__ int sc[256];
    __shared__ int sSel, sKth, sCnt, sMin;
    __shared__ int sIdx[128];

    unsigned prefix = 0, pmask = 0;
    int kth = 128;
    for (int shift = 24; shift >= 0; shift -= 8) {
        if (tid < 256) hist[tid] = 0;
        __syncthreads();
        #pragma unroll
        for (int k = 0; k < 16; k++)
            if ((key[k] & pmask) == prefix)
                atomicAdd(&hist[(key[k] >> shift) & 255], 1);
        __syncthreads();
        if (tid < 256) sc[tid] = hist[tid];
        __syncthreads();
        #pragma unroll
        for (int d = 1; d < 256; d <<= 1) {
            int t = 0;
            if (tid < 256 && tid + d < 256) t = sc[tid + d];
            __syncthreads();
            if (tid < 256) sc[tid] += t;
            __syncthreads();
        }
        if (tid < 256) {
            int cum = sc[tid];
            int nxt = (tid < 255) ? sc[tid + 1] : 0;
            if (cum >= kth && nxt < kth) { sSel = tid; sKth = kth - nxt; }
        }
        __syncthreads();
        prefix |= ((unsigned)sSel) << shift;
        pmask  |= 0xFFu << shift;
        kth = sKth;
        __syncthreads();
    }
    if (tid == 0) sCnt = 0;
    __syncthreads();
    #pragma unroll
    for (int k = 0; k < 16; k++)
        if (key[k] > prefix) {
            int p = atomicAdd(&sCnt, 1);
            sIdx[p] = tid + (k << 9);
        }
    __syncthreads();
    int ngt = sCnt;
    int need = 128 - ngt;
    int last = -1;
    for (int s = 0; s < need; s++) {
        if (tid == 0) sMin = 0x7FFFFFFF;
        __syncthreads();
        #pragma unroll
        for (int k = 0; k < 16; k++) {
            if (key[k] == prefix) {
                int id2 = tid + (k << 9);
                if (id2 > last) atomicMin(&sMin, id2);
            }
        }
        __syncthreads();
        int m = sMin;
        if (tid == 0) sIdx[ngt + s] = m;
        last = m;
        __syncthreads();
    }
    for (int sz = 2; sz <= 128; sz <<= 1) {
        for (int st = sz >> 1; st > 0; st >>= 1) {
            if (tid < 128) {
                int i = tid, ixj = i ^ st;
                if (ixj > i) {
                    int a = sIdx[i], b2 = sIdx[ixj];
                    bool up = ((i & sz) == 0);
                    if ((a > b2) == up) { sIdx[i] = b2; sIdx[ixj] = a; }
                }
            }
            __syncthreads();
        }
    }
    if (tid < 128) g_idx[row * W_ + tid] = sIdx[tid];
}

// ---------------- fused gather + HMMA attention + scatter ----------------
// SMEM byte offsets (regions phase-reused)
#define OFF_AHI   0u          // bf16 Q hi   [128][72] k-major
#define OFF_ALO   18432u      // bf16 Q lo
#define OFF_BHI   36864u      // bf16 K^ hi
#define OFF_BLO   55296u      // bf16 K^ lo
#define OFF_R     73728u      // bf16 rel_w  [128][72]
#define OFF_VTHI  92160u      // bf16 V^T hi [64][136]
#define OFF_VTLO  109568u     // bf16 V^T lo
#define OFF_QF    126976u     // fp32 Q stage [128][68] (overlaid by sD)
#define OFF_D     126976u     // fp32 logits/P [128][132]
#define OFF_PHI   0u          // bf16 P hi [128][136] (overlays A/B)
#define OFF_PLO   34816u      // bf16 P lo
#define OFF_INV   194560u
#define OFF_IDXS  195072u
#define SMEM_ATTN_BYTES 195584u

#define STR_AB 72
#define STR_VT 136
#define STR_P  136
#define STR_D  132

__global__ void __launch_bounds__(256)
k_attn(const float* __restrict__ qk,
       const float* __restrict__ vv,
       const float* __restrict__ relw,
       float* __restrict__ outNum) {
    extern __shared__ char sm[];
    float* sQf  = (float*)(sm + OFF_QF);
    float* sD   = (float*)(sm + OFF_D);
    float* sInv = (float*)(sm + OFF_INV);
    int*   sIdx = (int*)(sm + OFF_IDXS);

    int bhc = blockIdx.x;
    int bh = bhc >> 6;
    int h = bh & (H_ - 1);
    int tid = threadIdx.x;

    if (tid < 128) sIdx[tid] = g_idx[bhc * W_ + tid];
    __syncthreads();

    // ---- gather: q -> fp32 stage; v -> V^T bf16 hi/lo; rel -> bf16 ----
    for (int i = tid; i < 128 * 16; i += 256) {
        int r = i >> 4, c4 = (i & 15) << 2;
        int tok = sIdx[r];
        float4 q4 = *(const float4*)(qk + ((size_t)bh * T_ + tok) * D_ + c4);
        sQf[r * 68 + c4 + 0] = q4.x; sQf[r * 68 + c4 + 1] = q4.y;
        sQf[r * 68 + c4 + 2] = q4.z; sQf[r * 68 + c4 + 3] = q4.w;

        float4 v4 = *(const float4*)(vv + ((size_t)bh * T_ + tok) * D_ + c4);
        float vval[4] = {v4.x, v4.y, v4.z, v4.w};
        #pragma unroll
        for (int j = 0; j < 4; j++) {
            int d = c4 + j;
            __nv_bfloat16 hi = __float2bfloat16_rn(vval[j]);
            float lo = vval[j] - __bfloat162float(hi);
            uint32_t off = (uint32_t)(d * STR_VT + r) * 2;
            *(__nv_bfloat16*)(sm + OFF_VTHI + off) = hi;
            *(__nv_bfloat16*)(sm + OFF_VTLO + off) = __float2bfloat16_rn(lo);
        }
        float4 r4 = *(const float4*)(relw + ((size_t)r * H_ + h) * D_ + c4);
        uint32_t ro = (uint32_t)(r * STR_AB + c4) * 2;
        *(uint32_t*)(sm + OFF_R + ro)     = packbf(__float2bfloat16_rn(r4.x), __float2bfloat16_rn(r4.y));
        *(uint32_t*)(sm + OFF_R + ro + 4) = packbf(__float2bfloat16_rn(r4.z), __float2bfloat16_rn(r4.w));
    }
    __syncthreads();

    // ---- inverse norms ----
    if (tid < 128) {
        float s = 0.f;
        #pragma unroll
        for (int k4 = 0; k4 < 16; k4++) {
            float4 x = *(const float4*)(sQf + tid * 68 + k4 * 4);
            s += x.x * x.x + x.y * x.y + x.z * x.z + x.w * x.w;
        }
        sInv[tid] = 1.f / fmaxf(sqrtf(s), 1e-12f);
    }
    __syncthreads();

    // ---- build A (q hi/lo) and B (normalized k hi/lo), k-major stride 72 ----
    for (int i = tid; i < 128 * 32; i += 256) {
        int r = i >> 5, kp = i & 31, k = kp << 1;
        float q0 = sQf[r * 68 + k], q1 = sQf[r * 68 + k + 1];
        float inv = sInv[r];
        __nv_bfloat16 ah0 = __float2bfloat16_rn(q0), ah1 = __float2bfloat16_rn(q1);
        float al0 = q0 - __bfloat162float(ah0), al1 = q1 - __bfloat162float(ah1);
        float b0 = q0 * inv, b1 = q1 * inv;
        __nv_bfloat16 bh0 = __float2bfloat16_rn(b0), bh1 = __float2bfloat16_rn(b1);
        float bl0 = b0 - __bfloat162float(bh0), bl1 = b1 - __bfloat162float(bh1);
        uint32_t off = (uint32_t)(r * STR_AB + k) * 2;
        *(uint32_t*)(sm + OFF_AHI + off) = packbf(ah0, ah1);
        *(uint32_t*)(sm + OFF_ALO + off) = packbf(__float2bfloat16_rn(al0), __float2bfloat16_rn(al1));
        *(uint32_t*)(sm + OFF_BHI + off) = packbf(bh0, bh1);
        *(uint32_t*)(sm + OFF_BLO + off) = packbf(bl0 == bl0 ? __float2bfloat16_rn(bl0) : __float2bfloat16_rn(0.f),
                                                  __float2bfloat16_rn(bl1));
    }
    __syncthreads();

    const int lane = tid & 31, warp = tid >> 5;
    const int qr = lane >> 2, qc = (lane & 3) << 1;
    const int m0 = warp << 4;
    const float scale = 0.125f;

    // ---- GEMM1: dots = Q . K^T (3-term split) ----
    {
        float acc[16][4];
        #pragma unroll
        for (int nt = 0; nt < 16; nt++)
            #pragma unroll
            for (int u = 0; u < 4; u++) acc[nt][u] = 0.f;

        #pragma unroll
        for (int kt = 0; kt < 4; kt++) {
            int ka = kt * 16 + qc;
            uint32_t ah[4], al[4];
            uint32_t a0o = (uint32_t)((m0 + qr) * STR_AB + ka) * 2;
            uint32_t a1o = (uint32_t)((m0 + qr + 8) * STR_AB + ka) * 2;
            ah[0] = *(uint32_t*)(sm + OFF_AHI + a0o);
            ah[1] = *(uint32_t*)(sm + OFF_AHI + a1o);
            ah[2] = *(uint32_t*)(sm + OFF_AHI + a0o + 16);
            ah[3] = *(uint32_t*)(sm + OFF_AHI + a1o + 16);
            al[0] = *(uint32_t*)(sm + OFF_ALO + a0o);
            al[1] = *(uint32_t*)(sm + OFF_ALO + a1o);
            al[2] = *(uint32_t*)(sm + OFF_ALO + a0o + 16);
            al[3] = *(uint32_t*)(sm + OFF_ALO + a1o + 16);
            #pragma unroll
            for (int nt = 0; nt < 16; nt++) {
                uint32_t bo = (uint32_t)((nt * 8 + qr) * STR_AB + ka) * 2;
                uint32_t bh0 = *(uint32_t*)(sm + OFF_BHI + bo);
                uint32_t bh1 = *(uint32_t*)(sm + OFF_BHI + bo + 16);
                uint32_t bl0 = *(uint32_t*)(sm + OFF_BLO + bo);
                uint32_t bl1 = *(uint32_t*)(sm + OFF_BLO + bo + 16);
                mma_bf16(acc[nt], ah, bh0, bh1);
                mma_bf16(acc[nt], ah, bl0, bl1);
                mma_bf16(acc[nt], al, bh0, bh1);
            }
        }
        #pragma unroll
        for (int nt = 0; nt < 16; nt++) {
            int col = nt * 8 + qc;
            sD[(m0 + qr) * STR_D + col]     = acc[nt][0] * scale;
            sD[(m0 + qr) * STR_D + col + 1] = acc[nt][1] * scale;
            sD[(m0 + qr + 8) * STR_D + col]     = acc[nt][2] * scale;
            sD[(m0 + qr + 8) * STR_D + col + 1] = acc[nt][3] * scale;
        }
    }
    __syncwarp();

    // ---- GEMM2: rel = Q . rel_w^T, shifted add into sD ----
    {
        float acc[16][4];
        #pragma unroll
        for (int nt = 0; nt < 16; nt++)
            #pragma unroll
            for (int u = 0; u < 4; u++) acc[nt][u] = 0.f;

        #pragma unroll
        for (int kt = 0; kt < 4; kt++) {
            int ka = kt * 16 + qc;
            uint32_t ah[4];
            uint32_t a0o = (uint32_t)((m0 + qr) * STR_AB + ka) * 2;
            uint32_t a1o = (uint32_t)((m0 + qr + 8) * STR_AB + ka) * 2;
            ah[0] = *(uint32_t*)(sm + OFF_AHI + a0o);
            ah[1] = *(uint32_t*)(sm + OFF_AHI + a1o);
            ah[2] = *(uint32_t*)(sm + OFF_AHI + a0o + 16);
            ah[3] = *(uint32_t*)(sm + OFF_AHI + a1o + 16);
            #pragma unroll
            for (int nt = 0; nt < 16; nt++) {
                uint32_t bo = (uint32_t)((nt * 8 + qr) * STR_AB + ka) * 2;
                uint32_t br0 = *(uint32_t*)(sm + OFF_R + bo);
                uint32_t br1 = *(uint32_t*)(sm + OFF_R + bo + 16);
                mma_bf16(acc[nt], ah, br0, br1);
            }
        }
        #pragma unroll
        for (int nt = 0; nt < 16; nt++) {
            int jj = nt * 8 + qc;
            int i0 = m0 + qr;
            int j0 = i0 + jj - 127;
            if (j0 >= 0)     sD[i0 * STR_D + j0]     += acc[nt][0] * scale;
            if (j0 + 1 >= 0 && j0 + 1 <= i0) sD[i0 * STR_D + j0 + 1] += acc[nt][1] * scale;
            int i1 = i0 + 8;
            int j1 = i1 + jj - 127;
            if (j1 >= 0)     sD[i1 * STR_D + j1]     += acc[nt][2] * scale;
            if (j1 + 1 >= 0 && j1 + 1 <= i1) sD[i1 * STR_D + j1 + 1] += acc[nt][3] * scale;
        }
    }
    __syncthreads();

    // ---- softmax (2 threads per row, diag=-50000 inline) ----
    {
        int r = tid >> 1, hf = tid & 1;
        float* rowp = sD + r * STR_D + hf * 64;
        int dcol = r - hf * 64;   // local index of diagonal if in this half
        float mx = -1e30f;
        #pragma unroll 4
        for (int j = 0; j < 64; j++) {
            float x = (j == dcol) ? -50000.0f : rowp[j];
            mx = fmaxf(mx, x);
        }
        mx = fmaxf(mx, __shfl_xor_sync(0xFFFFFFFFu, mx, 1));
        float s = 0.f;
        #pragma unroll 4
        for (int j = 0; j < 64; j++) {
            float x = (j == dcol) ? -50000.0f : rowp[j];
            float e = expf(x - mx);
            rowp[j] = e;
            s += e;
        }
        s += __shfl_xor_sync(0xFFFFFFFFu, s, 1);
        float is = 1.f / s;
        #pragma unroll 4
        for (int j = 0; j < 64; j++) rowp[j] *= is;
    }
    __syncthreads();

    // ---- convert P -> bf16 hi/lo, k-major stride 136 (overlays A/B) ----
    for (int i = tid; i < 128 * 64; i += 256) {
        int r = i >> 6, kp = i & 63, k = kp << 1;
        float p0 = sD[r * STR_D + k], p1 = sD[r * STR_D + k + 1];
        __nv_bfloat16 h0 = __float2bfloat16_rn(p0), h1 = __float2bfloat16_rn(p1);
        float l0 = p0 - __bfloat162float(h0), l1 = p1 - __bfloat162float(h1);
        uint32_t off = (uint32_t)(r * STR_P + k) * 2;
        *(uint32_t*)(sm + OFF_PHI + off) = packbf(h0, h1);
        *(uint32_t*)(sm + OFF_PLO + off) = packbf(__float2bfloat16_rn(l0), __float2bfloat16_rn(l1));
    }
    __syncthreads();

    // ---- GEMM3: AV (3-term split), scatter from fragments ----
    {
        float acc[8][4];
        #pragma unroll
        for (int nt = 0; nt < 8; nt++)
            #pragma unroll
            for (int u = 0; u < 4; u++) acc[nt][u] = 0.f;

        #pragma unroll
        for (int kt = 0; kt < 8; kt++) {
            int ka = kt * 16 + qc;
            uint32_t ah[4], al[4];
            uint32_t a0o = (uint32_t)((m0 + qr) * STR_P + ka) * 2;
            uint32_t a1o = (uint32_t)((m0 + qr + 8) * STR_P + ka) * 2;
            ah[0] = *(uint32_t*)(sm + OFF_PHI + a0o);
            ah[1] = *(uint32_t*)(sm + OFF_PHI + a1o);
            ah[2] = *(uint32_t*)(sm + OFF_PHI + a0o + 16);
            ah[3] = *(uint32_t*)(sm + OFF_PHI + a1o + 16);
            al[0] = *(uint32_t*)(sm + OFF_PLO + a0o);
            al[1] = *(uint32_t*)(sm + OFF_PLO + a1o);
            al[2] = *(uint32_t*)(sm + OFF_PLO + a0o + 16);
            al[3] = *(uint32_t*)(sm + OFF_PLO + a1o + 16);
            #pragma unroll
            for (int nt = 0; nt < 8; nt++) {
                uint32_t bo = (uint32_t)((nt * 8 + qr) * STR_VT + ka) * 2;
                uint32_t bh0 = *(uint32_t*)(sm + OFF_VTHI + bo);
                uint32_t bh1 = *(uint32_t*)(sm + OFF_VTHI + bo + 16);
                uint32_t bl0 = *(uint32_t*)(sm + OFF_VTLO + bo);
                uint32_t bl1 = *(uint32_t*)(sm + OFF_VTLO + bo + 16);
                mma_bf16(acc[nt], ah, bh0, bh1);
                mma_bf16(acc[nt], ah, bl0, bl1);
                mma_bf16(acc[nt], al, bh0, bh1);
            }
        }
        int tok0 = sIdx[m0 + qr];
        int tok1 = sIdx[m0 + qr + 8];
        float* op0 = outNum + ((size_t)bh * T_ + tok0) * D_;
        float* op1 = outNum + ((size_t)bh * T_ + tok1) * D_;
        #pragma unroll
        for (int nt = 0; nt < 8; nt++) {
            int col = nt * 8 + qc;
            atomicAdd((float2*)(op0 + col), make_float2(acc[nt][0], acc[nt][1]));
            atomicAdd((float2*)(op1 + col), make_float2(acc[nt][2], acc[nt][3]));
        }
    }
    if (tid < 128) atomicAdd(&g_den[(size_t)bh * T_ + sIdx[tid]], 1.0f);
}

// ---------------- normalize out = num/(den+eps); write loss ----------------
__global__ void k_norm(float* __restrict__ out, int has_loss) {
    size_t gid = (size_t)blockIdx.x * 256 + threadIdx.x;
    float den = g_den[gid >> 4];
    float s = 1.f / (den + 1e-5f);
    float4* o4 = (float4*)out;
    float4 v = o4[gid];
    v.x *= s; v.y *= s; v.z *= s; v.w *= s;
    o4[gid] = v;
    if (gid == 0 && has_loss)
        out[(size_t)BH_ * T_ * D_] = g_loss * (0.0001f / (float)((size_t)BH_ * T_ * D_));
}

// ---------------- launch ----------------
extern "C" void kernel_launch(void* const* d_in, const int* in_sizes, int n_in,
                              void* d_out, int out_size) {
    const float* qk    = (const float*)d_in[0];
    const float* v     = (const float*)d_in[1];
    const float* means = (const float*)d_in[2];
    const float* relw  = (const float*)d_in[3];
    if (n_in >= 4 && in_sizes[2] == W_ * H_ * D_ && in_sizes[3] == H_ * C_ * D_) {
        relw  = (const float*)d_in[2];
        means = (const float*)d_in[3];
    }
    float* out = (float*)d_out;

    cudaMemsetAsync(d_out, 0, (size_t)out_size * sizeof(float), 0);
    k_zero<<<(BH_ * T_ + 255) / 256, 256>>>();

    dim3 g1(T_ / 64, BH_);
    k_dists<<<g1, 256>>>(qk, means);

    k_topk<<<BH_ * C_, 512>>>();

    cudaFuncSetAttribute(k_attn, cudaFuncAttributeMaxDynamicSharedMemorySize, SMEM_ATTN_BYTES);
    k_attn<<<BH_ * C_, 256, SMEM_ATTN_BYTES>>>(qk, v, relw, out);

    int nf4 = BH_ * T_ * D_ / 4;
    k_norm<<<nf4 / 256, 256>>>(out, out_size > BH_ * T_ * D_ ? 1 : 0);
}

// round 5
// speedup vs baseline: 1.5264x; 1.0509x over previous
#include <cuda_runtime.h>
#include <cuda_bf16.h>
#include <cstdint>
#include <math.h>

#define B_ 4
#define H_ 8
#define T_ 8192
#define D_ 64
#define C_ 64
#define W_ 128
#define BH_ (B_*H_)

// ---------------- scratch ----------------
__device__ float g_dists[(size_t)BH_ * C_ * T_];   // [bh][c][t]
__device__ int   g_idx[BH_ * C_ * W_];
__device__ float g_den[BH_ * T_];
__device__ float g_loss;

__device__ __forceinline__ uint32_t packbf(__nv_bfloat16 a, __nv_bfloat16 b) {
    return ((uint32_t)__bfloat16_as_ushort(b) << 16) | (uint32_t)__bfloat16_as_ushort(a);
}
__device__ __forceinline__ void mma_bf16(float (&c)[4], const uint32_t (&a)[4],
                                         uint32_t b0, uint32_t b1) {
    asm volatile("mma.sync.aligned.m16n8k16.row.col.f32.bf16.bf16.f32 "
        "{%0,%1,%2,%3}, {%4,%5,%6,%7}, {%8,%9}, {%0,%1,%2,%3};"
        : "+f"(c[0]), "+f"(c[1]), "+f"(c[2]), "+f"(c[3])
        : "r"(a[0]), "r"(a[1]), "r"(a[2]), "r"(a[3]), "r"(b0), "r"(b1));
}
__device__ __forceinline__ void ldsm4(uint32_t (&r)[4], uint32_t addr) {
    asm volatile("ldmatrix.sync.aligned.m8n8.x4.shared.b16 {%0,%1,%2,%3}, [%4];"
        : "=r"(r[0]), "=r"(r[1]), "=r"(r[2]), "=r"(r[3]) : "r"(addr));
}
__device__ __forceinline__ uint32_t smem_u32(const void* p) {
    uint32_t a;
    asm("{ .reg .u64 t; cvta.to.shared.u64 t, %1; cvt.u32.u64 %0, t; }" : "=r"(a) : "l"(p));
    return a;
}

// ---------------- zero den/loss ----------------
__global__ void k_zero() {
    int i = blockIdx.x * blockDim.x + threadIdx.x;
    if (i < BH_ * T_) g_den[i] = 0.f;
    if (i == 0) g_loss = 0.f;
}

// ---------------- dists = l2norm(qk) . means, fused commitment loss ----------------
__global__ void __launch_bounds__(256) k_dists(const float* __restrict__ qk,
                                               const float* __restrict__ means) {
    __shared__ float sQ[64 * 65];
    __shared__ float sM[64 * 65];
    __shared__ float sInv[64];
    int bh = blockIdx.y;
    int h = bh & (H_ - 1);
    int t0 = blockIdx.x * 64;
    const float* qp = qk + ((size_t)bh * T_ + t0) * D_;
    const float* mp = means + (size_t)h * C_ * D_;
    int tid = threadIdx.x;

    for (int i = tid; i < 64 * 16; i += 256) {
        int r = i >> 4, c4 = (i & 15) << 2;
        float4 a = *(const float4*)(qp + r * D_ + c4);
        sQ[r * 65 + c4 + 0] = a.x; sQ[r * 65 + c4 + 1] = a.y;
        sQ[r * 65 + c4 + 2] = a.z; sQ[r * 65 + c4 + 3] = a.w;
        float4 m = *(const float4*)(mp + r * D_ + c4);
        sM[r * 65 + c4 + 0] = m.x; sM[r * 65 + c4 + 1] = m.y;
        sM[r * 65 + c4 + 2] = m.z; sM[r * 65 + c4 + 3] = m.w;
    }
    __syncthreads();
    if (tid < 64) {
        float s = 0.f;
        #pragma unroll
        for (int k = 0; k < 64; k++) { float x = sQ[tid * 65 + k]; s += x * x; }
        sInv[tid] = 1.f / fmaxf(sqrtf(s), 1e-12f);
    }
    __syncthreads();

    int ty = tid >> 4, tx = tid & 15;
    float acc[4][4];
    #pragma unroll
    for (int u = 0; u < 4; u++)
        #pragma unroll
        for (int w = 0; w < 4; w++) acc[u][w] = 0.f;

    for (int k = 0; k < 64; k++) {
        float a[4], b[4];
        #pragma unroll
        for (int u = 0; u < 4; u++) a[u] = sQ[(ty * 4 + u) * 65 + k];
        #pragma unroll
        for (int w = 0; w < 4; w++) b[w] = sM[(tx * 4 + w) * 65 + k];
        #pragma unroll
        for (int u = 0; u < 4; u++)
            #pragma unroll
            for (int w = 0; w < 4; w++) acc[u][w] += a[u] * b[w];
    }
    __syncthreads();
    #pragma unroll
    for (int u = 0; u < 4; u++)
        #pragma unroll
        for (int w = 0; w < 4; w++)
            sQ[(tx * 4 + w) * 65 + (ty * 4 + u)] = acc[u][w] * sInv[ty * 4 + u];
    __syncthreads();
    float* dst = &g_dists[((size_t)bh * C_) * T_ + t0];
    for (int i = tid; i < 4096; i += 256) {
        int c = i >> 6, r = i & 63;
        dst[(size_t)c * T_ + r] = sQ[c * 65 + r];
    }
    if (tid < 64) {
        float m = -1e30f;
        #pragma unroll 8
        for (int c = 0; c < 64; c++) m = fmaxf(m, sQ[c * 65 + tid]);
        float v = 2.f - 2.f * m;
        #pragma unroll
        for (int off = 16; off > 0; off >>= 1) v += __shfl_down_sync(0xFFFFFFFFu, v, off);
        if ((tid & 31) == 0) atomicAdd(&g_loss, v);
    }
}

// ---------------- exact top-128 per (bh,c) row + ascending index sort ----------------
__global__ void __launch_bounds__(512) k_topk() {
    int row = blockIdx.x;
    const float* dp = g_dists + (size_t)row * T_;
    int tid = threadIdx.x;
    unsigned key[16];
    #pragma unroll
    for (int k = 0; k < 16; k++) {
        unsigned u = __float_as_uint(dp[tid + (k << 9)]);
        key[k] = (u & 0x80000000u) ? ~u : (u | 0x80000000u);
    }
    __shared__ int hist[256];
    __shared__ int sc[256];
    __shared__ int sSel, sKth, sCnt, sMin;
    __shared__ int sIdx[128];

    unsigned prefix = 0, pmask = 0;
    int kth = 128;
    for (int shift = 24; shift >= 0; shift -= 8) {
        if (tid < 256) hist[tid] = 0;
        __syncthreads();
        #pragma unroll
        for (int k = 0; k < 16; k++)
            if ((key[k] & pmask) == prefix)
                atomicAdd(&hist[(key[k] >> shift) & 255], 1);
        __syncthreads();
        if (tid < 256) sc[tid] = hist[tid];
        __syncthreads();
        #pragma unroll
        for (int d = 1; d < 256; d <<= 1) {
            int t = 0;
            if (tid < 256 && tid + d < 256) t = sc[tid + d];
            __syncthreads();
            if (tid < 256) sc[tid] += t;
            __syncthreads();
        }
        if (tid < 256) {
            int cum = sc[tid];
            int nxt = (tid < 255) ? sc[tid + 1] : 0;
            if (cum >= kth && nxt < kth) { sSel = tid; sKth = kth - nxt; }
        }
        __syncthreads();
        prefix |= ((unsigned)sSel) << shift;
        pmask  |= 0xFFu << shift;
        kth = sKth;
        __syncthreads();
    }
    if (tid == 0) sCnt = 0;
    __syncthreads();
    #pragma unroll
    for (int k = 0; k < 16; k++)
        if (key[k] > prefix) {
            int p = atomicAdd(&sCnt, 1);
            sIdx[p] = tid + (k << 9);
        }
    __syncthreads();
    int ngt = sCnt;
    int need = 128 - ngt;
    int last = -1;
    for (int s = 0; s < need; s++) {
        if (tid == 0) sMin = 0x7FFFFFFF;
        __syncthreads();
        #pragma unroll
        for (int k = 0; k < 16; k++) {
            if (key[k] == prefix) {
                int id2 = tid + (k << 9);
                if (id2 > last) atomicMin(&sMin, id2);
            }
        }
        __syncthreads();
        int m = sMin;
        if (tid == 0) sIdx[ngt + s] = m;
        last = m;
        __syncthreads();
    }
    for (int sz = 2; sz <= 128; sz <<= 1) {
        for (int st = sz >> 1; st > 0; st >>= 1) {
            if (tid < 128) {
                int i = tid, ixj = i ^ st;
                if (ixj > i) {
                    int a = sIdx[i], b2 = sIdx[ixj];
                    bool up = ((i & sz) == 0);
                    if ((a > b2) == up) { sIdx[i] = b2; sIdx[ixj] = a; }
                }
            }
            __syncthreads();
        }
    }
    if (tid < 128) g_idx[row * W_ + tid] = sIdx[tid];
}

// ---------------- fused gather + HMMA(ldmatrix) attention + scatter ----------------
#define OFF_AHI   0u          // bf16 Q hi   [128][72] k-major
#define OFF_ALO   18432u      // bf16 Q lo
#define OFF_BHI   36864u      // bf16 K^ hi
#define OFF_BLO   55296u      // bf16 K^ lo
#define OFF_R     73728u      // bf16 rel_w  [128][72]
#define OFF_VTHI  92160u      // bf16 V^T hi [64][136]
#define OFF_VTLO  109568u     // bf16 V^T lo
#define OFF_QF    126976u     // fp32 Q stage [128][68] (overlaid by sD)
#define OFF_D     126976u     // fp32 logits/P [128][132]
#define OFF_PHI   0u          // bf16 P hi [128][136] (overlays A/B)
#define OFF_PLO   34816u      // bf16 P lo
#define OFF_INV   194560u
#define OFF_IDXS  195072u
#define SMEM_ATTN_BYTES 195584u

#define STR_AB 72
#define STR_VT 136
#define STR_P  136
#define STR_D  132

__global__ void __launch_bounds__(512)
k_attn(const float* __restrict__ qk,
       const float* __restrict__ vv,
       const float* __restrict__ relw,
       float* __restrict__ outNum) {
    extern __shared__ char sm[];
    float* sQf  = (float*)(sm + OFF_QF);
    float* sD   = (float*)(sm + OFF_D);
    float* sInv = (float*)(sm + OFF_INV);
    int*   sIdx = (int*)(sm + OFF_IDXS);
    uint32_t sbase = smem_u32(sm);

    int bhc = blockIdx.x;
    int bh = bhc >> 6;
    int h = bh & (H_ - 1);
    int tid = threadIdx.x;

    if (tid < 128) sIdx[tid] = g_idx[bhc * W_ + tid];
    __syncthreads();

    // ---- gather: q -> fp32 stage; v -> V^T bf16 hi/lo; rel -> bf16 ----
    for (int i = tid; i < 128 * 16; i += 512) {
        int r = i >> 4, c4 = (i & 15) << 2;
        int tok = sIdx[r];
        float4 q4 = *(const float4*)(qk + ((size_t)bh * T_ + tok) * D_ + c4);
        sQf[r * 68 + c4 + 0] = q4.x; sQf[r * 68 + c4 + 1] = q4.y;
        sQf[r * 68 + c4 + 2] = q4.z; sQf[r * 68 + c4 + 3] = q4.w;

        float4 v4 = *(const float4*)(vv + ((size_t)bh * T_ + tok) * D_ + c4);
        float vval[4] = {v4.x, v4.y, v4.z, v4.w};
        #pragma unroll
        for (int j = 0; j < 4; j++) {
            int d = c4 + j;
            __nv_bfloat16 hi = __float2bfloat16_rn(vval[j]);
            float lo = vval[j] - __bfloat162float(hi);
            uint32_t off = (uint32_t)(d * STR_VT + r) * 2;
            *(__nv_bfloat16*)(sm + OFF_VTHI + off) = hi;
            *(__nv_bfloat16*)(sm + OFF_VTLO + off) = __float2bfloat16_rn(lo);
        }
        float4 r4 = *(const float4*)(relw + ((size_t)r * H_ + h) * D_ + c4);
        uint32_t ro = (uint32_t)(r * STR_AB + c4) * 2;
        *(uint32_t*)(sm + OFF_R + ro)     = packbf(__float2bfloat16_rn(r4.x), __float2bfloat16_rn(r4.y));
        *(uint32_t*)(sm + OFF_R + ro + 4) = packbf(__float2bfloat16_rn(r4.z), __float2bfloat16_rn(r4.w));
    }
    __syncthreads();

    if (tid < 128) {
        float s = 0.f;
        #pragma unroll
        for (int k4 = 0; k4 < 16; k4++) {
            float4 x = *(const float4*)(sQf + tid * 68 + k4 * 4);
            s += x.x * x.x + x.y * x.y + x.z * x.z + x.w * x.w;
        }
        sInv[tid] = 1.f / fmaxf(sqrtf(s), 1e-12f);
    }
    __syncthreads();

    // ---- build A (q hi/lo) and B (normalized k hi/lo), k-major stride 72 ----
    for (int i = tid; i < 128 * 32; i += 512) {
        int r = i >> 5, kp = i & 31, k = kp << 1;
        float q0 = sQf[r * 68 + k], q1 = sQf[r * 68 + k + 1];
        float inv = sInv[r];
        __nv_bfloat16 ah0 = __float2bfloat16_rn(q0), ah1 = __float2bfloat16_rn(q1);
        float al0 = q0 - __bfloat162float(ah0), al1 = q1 - __bfloat162float(ah1);
        float b0 = q0 * inv, b1 = q1 * inv;
        __nv_bfloat16 bh0 = __float2bfloat16_rn(b0), bh1 = __float2bfloat16_rn(b1);
        float bl0 = b0 - __bfloat162float(bh0), bl1 = b1 - __bfloat162float(bh1);
        uint32_t off = (uint32_t)(r * STR_AB + k) * 2;
        *(uint32_t*)(sm + OFF_AHI + off) = packbf(ah0, ah1);
        *(uint32_t*)(sm + OFF_ALO + off) = packbf(__float2bfloat16_rn(al0), __float2bfloat16_rn(al1));
        *(uint32_t*)(sm + OFF_BHI + off) = packbf(bh0, bh1);
        *(uint32_t*)(sm + OFF_BLO + off) = packbf(__float2bfloat16_rn(bl0), __float2bfloat16_rn(bl1));
    }
    __syncthreads();

    const int lane = tid & 31, warp = tid >> 5;
    const int qr = lane >> 2, qc = (lane & 3) << 1;
    const int half = warp & 1;           // column half (64 cols of logits / 32 of d)
    const int R0 = (warp >> 1) << 4;     // 16-row block
    const float scale = 0.125f;

    // lane->address components for ldmatrix
    const int aRow = R0 + (lane & 15);
    const int aKof = (lane >> 4) << 3;
    const int bRowOf = ((lane >> 4) << 3) + (lane & 7);
    const int bKof = ((lane >> 3) & 1) << 3;

    float acc[8][4];     // GEMM1 dots: 8 nt x 4
    float rac[8][4];     // GEMM2 rel
    #pragma unroll
    for (int nt = 0; nt < 8; nt++)
        #pragma unroll
        for (int u = 0; u < 4; u++) { acc[nt][u] = 0.f; rac[nt][u] = 0.f; }

    #pragma unroll
    for (int kt = 0; kt < 4; kt++) {
        int ka = kt * 16;
        uint32_t ah[4], al[4];
        uint32_t aAddr = sbase + OFF_AHI + (uint32_t)(aRow * STR_AB + ka + aKof) * 2;
        ldsm4(ah, aAddr);
        ldsm4(al, aAddr + (OFF_ALO - OFF_AHI));
        #pragma unroll
        for (int p = 0; p < 4; p++) {
            int n0 = half * 64 + p * 16;
            uint32_t bAddr = sbase + OFF_BHI + (uint32_t)((n0 + bRowOf) * STR_AB + ka + bKof) * 2;
            uint32_t bhv[4], blv[4], brv[4];
            ldsm4(bhv, bAddr);
            ldsm4(blv, bAddr + (OFF_BLO - OFF_BHI));
            ldsm4(brv, bAddr + (OFF_R - OFF_BHI));
            mma_bf16(acc[2 * p],     ah, bhv[0], bhv[1]);
            mma_bf16(acc[2 * p],     ah, blv[0], blv[1]);
            mma_bf16(acc[2 * p],     al, bhv[0], bhv[1]);
            mma_bf16(acc[2 * p + 1], ah, bhv[2], bhv[3]);
            mma_bf16(acc[2 * p + 1], ah, blv[2], blv[3]);
            mma_bf16(acc[2 * p + 1], al, bhv[2], bhv[3]);
            mma_bf16(rac[2 * p],     ah, brv[0], brv[1]);
            mma_bf16(rac[2 * p + 1], ah, brv[2], brv[3]);
        }
    }
    // store dots
    #pragma unroll
    for (int nt = 0; nt < 8; nt++) {
        int col = half * 64 + nt * 8 + qc;
        sD[(R0 + qr) * STR_D + col]         = acc[nt][0] * scale;
        sD[(R0 + qr) * STR_D + col + 1]     = acc[nt][1] * scale;
        sD[(R0 + qr + 8) * STR_D + col]     = acc[nt][2] * scale;
        sD[(R0 + qr + 8) * STR_D + col + 1] = acc[nt][3] * scale;
    }
    __syncthreads();
    // shifted rel add (each (row, target-col) has a unique source -> unique writer)
    #pragma unroll
    for (int nt = 0; nt < 8; nt++) {
        int jj = half * 64 + nt * 8 + qc;
        int i0 = R0 + qr;
        int j0 = i0 + jj - 127;
        if (j0 >= 0)                     sD[i0 * STR_D + j0]     += rac[nt][0] * scale;
        if (j0 + 1 >= 0 && j0 + 1 <= i0) sD[i0 * STR_D + j0 + 1] += rac[nt][1] * scale;
        int i1 = i0 + 8;
        int j1 = i1 + jj - 127;
        if (j1 >= 0)                     sD[i1 * STR_D + j1]     += rac[nt][2] * scale;
        if (j1 + 1 >= 0 && j1 + 1 <= i1) sD[i1 * STR_D + j1 + 1] += rac[nt][3] * scale;
    }
    __syncthreads();

    // ---- softmax: 4 threads per row, 32 cols each, diag=-50000 inline ----
    {
        int r = tid >> 2, q4 = tid & 3;
        float* rowp = sD + r * STR_D + q4 * 32;
        int dcol = r - q4 * 32;
        float mx = -1e30f;
        #pragma unroll 4
        for (int j = 0; j < 32; j++) {
            float x = (j == dcol) ? -50000.0f : rowp[j];
            mx = fmaxf(mx, x);
        }
        mx = fmaxf(mx, __shfl_xor_sync(0xFFFFFFFFu, mx, 1));
        mx = fmaxf(mx, __shfl_xor_sync(0xFFFFFFFFu, mx, 2));
        float s = 0.f;
        #pragma unroll 4
        for (int j = 0; j < 32; j++) {
            float x = (j == dcol) ? -50000.0f : rowp[j];
            float e = expf(x - mx);
            rowp[j] = e;
            s += e;
        }
        s += __shfl_xor_sync(0xFFFFFFFFu, s, 1);
        s += __shfl_xor_sync(0xFFFFFFFFu, s, 2);
        float is = 1.f / s;
        #pragma unroll 4
        for (int j = 0; j < 32; j++) rowp[j] *= is;
    }
    __syncthreads();

    // ---- convert P -> bf16 hi/lo, k-major stride 136 (overlays A/B) ----
    for (int i = tid; i < 128 * 64; i += 512) {
        int r = i >> 6, kp = i & 63, k = kp << 1;
        float p0 = sD[r * STR_D + k], p1 = sD[r * STR_D + k + 1];
        __nv_bfloat16 h0 = __float2bfloat16_rn(p0), h1 = __float2bfloat16_rn(p1);
        float l0 = p0 - __bfloat162float(h0), l1 = p1 - __bfloat162float(h1);
        uint32_t off = (uint32_t)(r * STR_P + k) * 2;
        *(uint32_t*)(sm + OFF_PHI + off) = packbf(h0, h1);
        *(uint32_t*)(sm + OFF_PLO + off) = packbf(__float2bfloat16_rn(l0), __float2bfloat16_rn(l1));
    }
    __syncthreads();

    // ---- GEMM3: AV (3-term split); warp = 16 rows x 32 d-cols ----
    {
        float av[4][4];
        #pragma unroll
        for (int nt = 0; nt < 4; nt++)
            #pragma unroll
            for (int u = 0; u < 4; u++) av[nt][u] = 0.f;

        #pragma unroll
        for (int kt = 0; kt < 8; kt++) {
            int ka = kt * 16;
            uint32_t ph[4], pl[4];
            uint32_t pAddr = sbase + OFF_PHI + (uint32_t)(aRow * STR_P + ka + aKof) * 2;
            ldsm4(ph, pAddr);
            ldsm4(pl, pAddr + (OFF_PLO - OFF_PHI));
            #pragma unroll
            for (int p = 0; p < 2; p++) {
                int n0 = half * 32 + p * 16;
                uint32_t vAddr = sbase + OFF_VTHI + (uint32_t)((n0 + bRowOf) * STR_VT + ka + bKof) * 2;
                uint32_t vh[4], vl[4];
                ldsm4(vh, vAddr);
                ldsm4(vl, vAddr + (OFF_VTLO - OFF_VTHI));
                mma_bf16(av[2 * p],     ph, vh[0], vh[1]);
                mma_bf16(av[2 * p],     ph, vl[0], vl[1]);
                mma_bf16(av[2 * p],     pl, vh[0], vh[1]);
                mma_bf16(av[2 * p + 1], ph, vh[2], vh[3]);
                mma_bf16(av[2 * p + 1], ph, vl[2], vl[3]);
                mma_bf16(av[2 * p + 1], pl, vh[2], vh[3]);
            }
        }
        int tok0 = sIdx[R0 + qr];
        int tok1 = sIdx[R0 + qr + 8];
        float* op0 = outNum + ((size_t)bh * T_ + tok0) * D_;
        float* op1 = outNum + ((size_t)bh * T_ + tok1) * D_;
        #pragma unroll
        for (int nt = 0; nt < 4; nt++) {
            int col = half * 32 + nt * 8 + qc;
            atomicAdd((float2*)(op0 + col), make_float2(av[nt][0], av[nt][1]));
            atomicAdd((float2*)(op1 + col), make_float2(av[nt][2], av[nt][3]));
        }
    }
    if (tid < 128) atomicAdd(&g_den[(size_t)bh * T_ + sIdx[tid]], 1.0f);
}

// ---------------- normalize out = num/(den+eps); write loss ----------------
__global__ void k_norm(float* __restrict__ out, int has_loss) {
    size_t gid = (size_t)blockIdx.x * 256 + threadIdx.x;
    float den = g_den[gid >> 4];
    float s = 1.f / (den + 1e-5f);
    float4* o4 = (float4*)out;
    float4 v = o4[gid];
    v.x *= s; v.y *= s; v.z *= s; v.w *= s;
    o4[gid] = v;
    if (gid == 0 && has_loss)
        out[(size_t)BH_ * T_ * D_] = g_loss * (0.0001f / (float)((size_t)BH_ * T_ * D_));
}

// ---------------- launch ----------------
extern "C" void kernel_launch(void* const* d_in, const int* in_sizes, int n_in,
                              void* d_out, int out_size) {
    const float* qk    = (const float*)d_in[0];
    const float* v     = (const float*)d_in[1];
    const float* means = (const float*)d_in[2];
    const float* relw  = (const float*)d_in[3];
    if (n_in >= 4 && in_sizes[2] == W_ * H_ * D_ && in_sizes[3] == H_ * C_ * D_) {
        relw  = (const float*)d_in[2];
        means = (const float*)d_in[3];
    }
    float* out = (float*)d_out;

    cudaMemsetAsync(d_out, 0, (size_t)out_size * sizeof(float), 0);
    k_zero<<<(BH_ * T_ + 255) / 256, 256>>>();

    dim3 g1(T_ / 64, BH_);
    k_dists<<<g1, 256>>>(qk, means);

    k_topk<<<BH_ * C_, 512>>>();

    cudaFuncSetAttribute(k_attn, cudaFuncAttributeMaxDynamicSharedMemorySize, SMEM_ATTN_BYTES);
    k_attn<<<BH_ * C_, 512, SMEM_ATTN_BYTES>>>(qk, v, relw, out);

    int nf4 = BH_ * T_ * D_ / 4;
    k_norm<<<nf4 / 256, 256>>>(out, out_size > BH_ * T_ * D_ ? 1 : 0);
}

// round 6
// speedup vs baseline: 1.6287x; 1.0670x over previous
#include <cuda_runtime.h>
#include <cuda_bf16.h>
#include <cstdint>
#include <math.h>

#define B_ 4
#define H_ 8
#define T_ 8192
#define D_ 64
#define C_ 64
#define W_ 128
#define BH_ (B_*H_)

// ---------------- scratch ----------------
__device__ float g_dists[(size_t)BH_ * C_ * T_];   // [bh][c][t]
__device__ int   g_idx[BH_ * C_ * W_];
__device__ float g_den[BH_ * T_];
__device__ float g_loss;

__device__ __forceinline__ uint32_t packbf(__nv_bfloat16 a, __nv_bfloat16 b) {
    return ((uint32_t)__bfloat16_as_ushort(b) << 16) | (uint32_t)__bfloat16_as_ushort(a);
}
__device__ __forceinline__ void split2(float x, float y, uint32_t& hi, uint32_t& lo) {
    __nv_bfloat16 hx = __float2bfloat16_rn(x), hy = __float2bfloat16_rn(y);
    hi = packbf(hx, hy);
    lo = packbf(__float2bfloat16_rn(x - __bfloat162float(hx)),
                __float2bfloat16_rn(y - __bfloat162float(hy)));
}
__device__ __forceinline__ void mma_bf16(float (&c)[4], const uint32_t (&a)[4],
                                         uint32_t b0, uint32_t b1) {
    asm volatile("mma.sync.aligned.m16n8k16.row.col.f32.bf16.bf16.f32 "
        "{%0,%1,%2,%3}, {%4,%5,%6,%7}, {%8,%9}, {%0,%1,%2,%3};"
        : "+f"(c[0]), "+f"(c[1]), "+f"(c[2]), "+f"(c[3])
        : "r"(a[0]), "r"(a[1]), "r"(a[2]), "r"(a[3]), "r"(b0), "r"(b1));
}
__device__ __forceinline__ void ldsm4(uint32_t (&r)[4], uint32_t addr) {
    asm volatile("ldmatrix.sync.aligned.m8n8.x4.shared.b16 {%0,%1,%2,%3}, [%4];"
        : "=r"(r[0]), "=r"(r[1]), "=r"(r[2]), "=r"(r[3]) : "r"(addr));
}
__device__ __forceinline__ void ldsm4t(uint32_t (&r)[4], uint32_t addr) {
    asm volatile("ldmatrix.sync.aligned.m8n8.x4.trans.shared.b16 {%0,%1,%2,%3}, [%4];"
        : "=r"(r[0]), "=r"(r[1]), "=r"(r[2]), "=r"(r[3]) : "r"(addr));
}
__device__ __forceinline__ uint32_t smem_u32(const void* p) {
    uint32_t a;
    asm("{ .reg .u64 t; cvta.to.shared.u64 t, %1; cvt.u32.u64 %0, t; }" : "=r"(a) : "l"(p));
    return a;
}

// ---------------- zero den/loss ----------------
__global__ void k_zero() {
    int i = blockIdx.x * blockDim.x + threadIdx.x;
    if (i < BH_ * T_) g_den[i] = 0.f;
    if (i == 0) g_loss = 0.f;
}

// ---------------- dists = l2norm(qk) . means, fused commitment loss ----------------
__global__ void __launch_bounds__(256) k_dists(const float* __restrict__ qk,
                                               const float* __restrict__ means) {
    __shared__ float sQ[64 * 65];
    __shared__ float sM[64 * 65];
    __shared__ float sInv[64];
    int bh = blockIdx.y;
    int h = bh & (H_ - 1);
    int t0 = blockIdx.x * 64;
    const float* qp = qk + ((size_t)bh * T_ + t0) * D_;
    const float* mp = means + (size_t)h * C_ * D_;
    int tid = threadIdx.x;

    for (int i = tid; i < 64 * 16; i += 256) {
        int r = i >> 4, c4 = (i & 15) << 2;
        float4 a = *(const float4*)(qp + r * D_ + c4);
        sQ[r * 65 + c4 + 0] = a.x; sQ[r * 65 + c4 + 1] = a.y;
        sQ[r * 65 + c4 + 2] = a.z; sQ[r * 65 + c4 + 3] = a.w;
        float4 m = *(const float4*)(mp + r * D_ + c4);
        sM[r * 65 + c4 + 0] = m.x; sM[r * 65 + c4 + 1] = m.y;
        sM[r * 65 + c4 + 2] = m.z; sM[r * 65 + c4 + 3] = m.w;
    }
    __syncthreads();
    if (tid < 64) {
        float s = 0.f;
        #pragma unroll
        for (int k = 0; k < 64; k++) { float x = sQ[tid * 65 + k]; s += x * x; }
        sInv[tid] = 1.f / fmaxf(sqrtf(s), 1e-12f);
    }
    __syncthreads();

    int ty = tid >> 4, tx = tid & 15;
    float acc[4][4];
    #pragma unroll
    for (int u = 0; u < 4; u++)
        #pragma unroll
        for (int w = 0; w < 4; w++) acc[u][w] = 0.f;

    for (int k = 0; k < 64; k++) {
        float a[4], b[4];
        #pragma unroll
        for (int u = 0; u < 4; u++) a[u] = sQ[(ty * 4 + u) * 65 + k];
        #pragma unroll
        for (int w = 0; w < 4; w++) b[w] = sM[(tx * 4 + w) * 65 + k];
        #pragma unroll
        for (int u = 0; u < 4; u++)
            #pragma unroll
            for (int w = 0; w < 4; w++) acc[u][w] += a[u] * b[w];
    }
    __syncthreads();
    #pragma unroll
    for (int u = 0; u < 4; u++)
        #pragma unroll
        for (int w = 0; w < 4; w++)
            sQ[(tx * 4 + w) * 65 + (ty * 4 + u)] = acc[u][w] * sInv[ty * 4 + u];
    __syncthreads();
    float* dst = &g_dists[((size_t)bh * C_) * T_ + t0];
    for (int i = tid; i < 4096; i += 256) {
        int c = i >> 6, r = i & 63;
        dst[(size_t)c * T_ + r] = sQ[c * 65 + r];
    }
    if (tid < 64) {
        float m = -1e30f;
        #pragma unroll 8
        for (int c = 0; c < 64; c++) m = fmaxf(m, sQ[c * 65 + tid]);
        float v = 2.f - 2.f * m;
        #pragma unroll
        for (int off = 16; off > 0; off >>= 1) v += __shfl_down_sync(0xFFFFFFFFu, v, off);
        if ((tid & 31) == 0) atomicAdd(&g_loss, v);
    }
}

// ---------------- exact top-128 per (bh,c) row + ascending index sort ----------------
__global__ void __launch_bounds__(512) k_topk() {
    int row = blockIdx.x;
    const float* dp = g_dists + (size_t)row * T_;
    int tid = threadIdx.x;
    unsigned key[16];
    #pragma unroll
    for (int k = 0; k < 16; k++) {
        unsigned u = __float_as_uint(dp[tid + (k << 9)]);
        key[k] = (u & 0x80000000u) ? ~u : (u | 0x80000000u);
    }
    __shared__ int hist[256];
    __shared__ int sc[256];
    __shared__ int sSel, sKth, sCnt, sMin;
    __shared__ int sIdx[128];

    unsigned prefix = 0, pmask = 0;
    int kth = 128;
    for (int shift = 24; shift >= 0; shift -= 8) {
        if (tid < 256) hist[tid] = 0;
        __syncthreads();
        #pragma unroll
        for (int k = 0; k < 16; k++)
            if ((key[k] & pmask) == prefix)
                atomicAdd(&hist[(key[k] >> shift) & 255], 1);
        __syncthreads();
        if (tid < 256) sc[tid] = hist[tid];
        __syncthreads();
        #pragma unroll
        for (int d = 1; d < 256; d <<= 1) {
            int t = 0;
            if (tid < 256 && tid + d < 256) t = sc[tid + d];
            __syncthreads();
            if (tid < 256) sc[tid] += t;
            __syncthreads();
        }
        if (tid < 256) {
            int cum = sc[tid];
            int nxt = (tid < 255) ? sc[tid + 1] : 0;
            if (cum >= kth && nxt < kth) { sSel = tid; sKth = kth - nxt; }
        }
        __syncthreads();
        prefix |= ((unsigned)sSel) << shift;
        pmask  |= 0xFFu << shift;
        kth = sKth;
        __syncthreads();
    }
    if (tid == 0) sCnt = 0;
    __syncthreads();
    #pragma unroll
    for (int k = 0; k < 16; k++)
        if (key[k] > prefix) {
            int p = atomicAdd(&sCnt, 1);
            sIdx[p] = tid + (k << 9);
        }
    __syncthreads();
    int ngt = sCnt;
    int need = 128 - ngt;
    int last = -1;
    for (int s = 0; s < need; s++) {
        if (tid == 0) sMin = 0x7FFFFFFF;
        __syncthreads();
        #pragma unroll
        for (int k = 0; k < 16; k++) {
            if (key[k] == prefix) {
                int id2 = tid + (k << 9);
                if (id2 > last) atomicMin(&sMin, id2);
            }
        }
        __syncthreads();
        int m = sMin;
        if (tid == 0) sIdx[ngt + s] = m;
        last = m;
        __syncthreads();
    }
    for (int sz = 2; sz <= 128; sz <<= 1) {
        for (int st = sz >> 1; st > 0; st >>= 1) {
            if (tid < 128) {
                int i = tid, ixj = i ^ st;
                if (ixj > i) {
                    int a = sIdx[i], b2 = sIdx[ixj];
                    bool up = ((i & sz) == 0);
                    if ((a > b2) == up) { sIdx[i] = b2; sIdx[ixj] = a; }
                }
            }
            __syncthreads();
        }
    }
    if (tid < 128) g_idx[row * W_ + tid] = sIdx[tid];
}

// ---------------- fused gather + HMMA attention + scatter ----------------
// bf16 arrays all [128][72]; fp32 sD [128][132] overlays the Q fp32 stage.
#define OFF_AHI   0u
#define OFF_ALO   18432u
#define OFF_R     36864u
#define OFF_VHI   55296u
#define OFF_VLO   73728u
#define OFF_QF    92160u
#define OFF_D     92160u
#define OFF_INV   159744u
#define OFF_IDXS  160256u
#define SMEM_ATTN_BYTES 160768u

#define STR_BF 72
#define STR_D  132

__global__ void __launch_bounds__(512)
k_attn(const float* __restrict__ qk,
       const float* __restrict__ vv,
       const float* __restrict__ relw,
       float* __restrict__ outNum) {
    extern __shared__ char sm[];
    float* sQf  = (float*)(sm + OFF_QF);
    float* sD   = (float*)(sm + OFF_D);
    float* sInv = (float*)(sm + OFF_INV);
    int*   sIdx = (int*)(sm + OFF_IDXS);
    uint32_t sbase = smem_u32(sm);

    int bhc = blockIdx.x;
    int bh = bhc >> 6;
    int h = bh & (H_ - 1);
    int tid = threadIdx.x;

    if (tid < 128) sIdx[tid] = g_idx[bhc * W_ + tid];
    __syncthreads();

    // ---- gather: q -> fp32 stage; v -> bf16 hi/lo row-major; rel -> bf16 ----
    for (int i = tid; i < 128 * 16; i += 512) {
        int r = i >> 4, c4 = (i & 15) << 2;
        int tok = sIdx[r];
        float4 q4 = *(const float4*)(qk + ((size_t)bh * T_ + tok) * D_ + c4);
        sQf[r * 68 + c4 + 0] = q4.x; sQf[r * 68 + c4 + 1] = q4.y;
        sQf[r * 68 + c4 + 2] = q4.z; sQf[r * 68 + c4 + 3] = q4.w;

        float4 v4 = *(const float4*)(vv + ((size_t)bh * T_ + tok) * D_ + c4);
        uint32_t off = (uint32_t)(r * STR_BF + c4) * 2;
        uint32_t hi0, lo0, hi1, lo1;
        split2(v4.x, v4.y, hi0, lo0);
        split2(v4.z, v4.w, hi1, lo1);
        *(uint32_t*)(sm + OFF_VHI + off)     = hi0;
        *(uint32_t*)(sm + OFF_VHI + off + 4) = hi1;
        *(uint32_t*)(sm + OFF_VLO + off)     = lo0;
        *(uint32_t*)(sm + OFF_VLO + off + 4) = lo1;

        float4 r4 = *(const float4*)(relw + ((size_t)r * H_ + h) * D_ + c4);
        *(uint32_t*)(sm + OFF_R + off)     = packbf(__float2bfloat16_rn(r4.x), __float2bfloat16_rn(r4.y));
        *(uint32_t*)(sm + OFF_R + off + 4) = packbf(__float2bfloat16_rn(r4.z), __float2bfloat16_rn(r4.w));
    }
    __syncthreads();

    if (tid < 128) {
        float s = 0.f;
        #pragma unroll
        for (int k4 = 0; k4 < 16; k4++) {
            float4 x = *(const float4*)(sQf + tid * 68 + k4 * 4);
            s += x.x * x.x + x.y * x.y + x.z * x.z + x.w * x.w;
        }
        sInv[tid] = 1.f / fmaxf(sqrtf(s), 1e-12f);
    }
    __syncthreads();

    // ---- build Q bf16 hi/lo (used as BOTH A and B of GEMM1 via symmetry) ----
    for (int i = tid; i < 128 * 32; i += 512) {
        int r = i >> 5, kp = i & 31, k = kp << 1;
        float q0 = sQf[r * 68 + k], q1 = sQf[r * 68 + k + 1];
        uint32_t hi, lo;
        split2(q0, q1, hi, lo);
        uint32_t off = (uint32_t)(r * STR_BF + k) * 2;
        *(uint32_t*)(sm + OFF_AHI + off) = hi;
        *(uint32_t*)(sm + OFF_ALO + off) = lo;
    }
    __syncthreads();

    const int lane = tid & 31, warp = tid >> 5;
    const int qr = lane >> 2, qc = (lane & 3) << 1;
    const float scale = 0.125f;

    const int aKof = (lane >> 4) << 3;
    const int aRowL = lane & 15;
    const int bRowOf = ((lane >> 4) << 3) + (lane & 7);
    const int bKof = ((lane >> 3) & 1) << 3;

    // ---- GEMM1+2: warp = 32 rows x 32 cols ----
    {
        const int R0 = (warp & 3) << 5;
        const int C0 = (warp >> 2) << 5;
        float acc[2][4][4], rac[2][4][4];
        #pragma unroll
        for (int rb = 0; rb < 2; rb++)
            #pragma unroll
            for (int nt = 0; nt < 4; nt++)
                #pragma unroll
                for (int u = 0; u < 4; u++) { acc[rb][nt][u] = 0.f; rac[rb][nt][u] = 0.f; }

        #pragma unroll
        for (int kt = 0; kt < 4; kt++) {
            int ka = kt * 16;
            uint32_t ah[2][4], al[2][4];
            #pragma unroll
            for (int rb = 0; rb < 2; rb++) {
                uint32_t aAddr = sbase + OFF_AHI + (uint32_t)((R0 + rb * 16 + aRowL) * STR_BF + ka + aKof) * 2;
                ldsm4(ah[rb], aAddr);
                ldsm4(al[rb], aAddr + (OFF_ALO - OFF_AHI));
            }
            #pragma unroll
            for (int p = 0; p < 2; p++) {
                uint32_t bAddr = sbase + OFF_AHI + (uint32_t)((C0 + p * 16 + bRowOf) * STR_BF + ka + bKof) * 2;
                uint32_t bhv[4], blv[4], brv[4];
                ldsm4(bhv, bAddr);
                ldsm4(blv, bAddr + (OFF_ALO - OFF_AHI));
                ldsm4(brv, bAddr + (OFF_R - OFF_AHI));
                #pragma unroll
                for (int rb = 0; rb < 2; rb++) {
                    mma_bf16(acc[rb][2 * p],     ah[rb], bhv[0], bhv[1]);
                    mma_bf16(acc[rb][2 * p],     ah[rb], blv[0], blv[1]);
                    mma_bf16(acc[rb][2 * p],     al[rb], bhv[0], bhv[1]);
                    mma_bf16(acc[rb][2 * p + 1], ah[rb], bhv[2], bhv[3]);
                    mma_bf16(acc[rb][2 * p + 1], ah[rb], blv[2], blv[3]);
                    mma_bf16(acc[rb][2 * p + 1], al[rb], bhv[2], bhv[3]);
                    mma_bf16(rac[rb][2 * p],     ah[rb], brv[0], brv[1]);
                    mma_bf16(rac[rb][2 * p + 1], ah[rb], brv[2], brv[3]);
                }
            }
        }
        // store dots, scaled by column inv-norm (symmetry trick)
        #pragma unroll
        for (int nt = 0; nt < 4; nt++) {
            int col = C0 + nt * 8 + qc;
            float i0v = sInv[col] * scale, i1v = sInv[col + 1] * scale;
            #pragma unroll
            for (int rb = 0; rb < 2; rb++) {
                int r0 = R0 + rb * 16 + qr;
                sD[r0 * STR_D + col]           = acc[rb][nt][0] * i0v;
                sD[r0 * STR_D + col + 1]       = acc[rb][nt][1] * i1v;
                sD[(r0 + 8) * STR_D + col]     = acc[rb][nt][2] * i0v;
                sD[(r0 + 8) * STR_D + col + 1] = acc[rb][nt][3] * i1v;
            }
        }
        __syncthreads();
        // shifted rel add
        #pragma unroll
        for (int nt = 0; nt < 4; nt++) {
            int jj = C0 + nt * 8 + qc;
            #pragma unroll
            for (int rb = 0; rb < 2; rb++) {
                int i0 = R0 + rb * 16 + qr;
                int j0 = i0 + jj - 127;
                if (j0 >= 0)                     sD[i0 * STR_D + j0]     += rac[rb][nt][0] * scale;
                if (j0 + 1 >= 0 && j0 + 1 <= i0) sD[i0 * STR_D + j0 + 1] += rac[rb][nt][1] * scale;
                int i1 = i0 + 8;
                int j1 = i1 + jj - 127;
                if (j1 >= 0)                     sD[i1 * STR_D + j1]     += rac[rb][nt][2] * scale;
                if (j1 + 1 >= 0 && j1 + 1 <= i1) sD[i1 * STR_D + j1 + 1] += rac[rb][nt][3] * scale;
            }
        }
    }
    __syncthreads();

    // ---- softmax: 4 threads per row, diag=-50000 inline ----
    {
        int r = tid >> 2, q4 = tid & 3;
        float* rowp = sD + r * STR_D + q4 * 32;
        int dcol = r - q4 * 32;
        float mx = -1e30f;
        #pragma unroll 4
        for (int j = 0; j < 32; j++) {
            float x = (j == dcol) ? -50000.0f : rowp[j];
            mx = fmaxf(mx, x);
        }
        mx = fmaxf(mx, __shfl_xor_sync(0xFFFFFFFFu, mx, 1));
        mx = fmaxf(mx, __shfl_xor_sync(0xFFFFFFFFu, mx, 2));
        float s = 0.f;
        #pragma unroll 4
        for (int j = 0; j < 32; j++) {
            float x = (j == dcol) ? -50000.0f : rowp[j];
            float e = expf(x - mx);
            rowp[j] = e;
            s += e;
        }
        s += __shfl_xor_sync(0xFFFFFFFFu, s, 1);
        s += __shfl_xor_sync(0xFFFFFFFFu, s, 2);
        float is = 1.f / s;
        #pragma unroll 4
        for (int j = 0; j < 32; j++) rowp[j] *= is;
    }
    __syncthreads();

    // ---- GEMM3: AV; A = P direct from sD (register split), B = V via ldsm.trans ----
    {
        const int R0g = (warp >> 1) << 4;
        const int chalf = warp & 1;
        float av[4][4];
        #pragma unroll
        for (int nt = 0; nt < 4; nt++)
            #pragma unroll
            for (int u = 0; u < 4; u++) av[nt][u] = 0.f;

        const int tKrow = ((lane >> 3) & 1) * 8 + (lane & 7);
        const int tDcol = ((lane >> 4) & 1) * 8;

        #pragma unroll
        for (int kt = 0; kt < 8; kt++) {
            int ka = kt * 16;
            int r0 = R0g + qr;
            float2 f0 = *(float2*)(sD + r0 * STR_D + ka + qc);
            float2 f1 = *(float2*)(sD + (r0 + 8) * STR_D + ka + qc);
            float2 f2 = *(float2*)(sD + r0 * STR_D + ka + 8 + qc);
            float2 f3 = *(float2*)(sD + (r0 + 8) * STR_D + ka + 8 + qc);
            uint32_t ph[4], pl[4];
            split2(f0.x, f0.y, ph[0], pl[0]);
            split2(f1.x, f1.y, ph[1], pl[1]);
            split2(f2.x, f2.y, ph[2], pl[2]);
            split2(f3.x, f3.y, ph[3], pl[3]);
            #pragma unroll
            for (int p = 0; p < 2; p++) {
                int n0 = chalf * 32 + p * 16;
                uint32_t vAddr = sbase + OFF_VHI + (uint32_t)((ka + tKrow) * STR_BF + n0 + tDcol) * 2;
                uint32_t vh[4], vl[4];
                ldsm4t(vh, vAddr);
                ldsm4t(vl, vAddr + (OFF_VLO - OFF_VHI));
                mma_bf16(av[2 * p],     ph, vh[0], vh[1]);
                mma_bf16(av[2 * p],     ph, vl[0], vl[1]);
                mma_bf16(av[2 * p],     pl, vh[0], vh[1]);
                mma_bf16(av[2 * p + 1], ph, vh[2], vh[3]);
                mma_bf16(av[2 * p + 1], ph, vl[2], vl[3]);
                mma_bf16(av[2 * p + 1], pl, vh[2], vh[3]);
            }
        }
        int tok0 = sIdx[R0g + qr];
        int tok1 = sIdx[R0g + qr + 8];
        float* op0 = outNum + ((size_t)bh * T_ + tok0) * D_;
        float* op1 = outNum + ((size_t)bh * T_ + tok1) * D_;
        #pragma unroll
        for (int nt = 0; nt < 4; nt++) {
            int col = chalf * 32 + nt * 8 + qc;
            atomicAdd((float2*)(op0 + col), make_float2(av[nt][0], av[nt][1]));
            atomicAdd((float2*)(op1 + col), make_float2(av[nt][2], av[nt][3]));
        }
    }
    if (tid < 128) atomicAdd(&g_den[(size_t)bh * T_ + sIdx[tid]], 1.0f);
}

// ---------------- normalize out = num/(den+eps); write loss ----------------
__global__ void k_norm(float* __restrict__ out, int has_loss) {
    size_t gid = (size_t)blockIdx.x * 256 + threadIdx.x;
    float den = g_den[gid >> 4];
    float s = 1.f / (den + 1e-5f);
    float4* o4 = (float4*)out;
    float4 v = o4[gid];
    v.x *= s; v.y *= s; v.z *= s; v.w *= s;
    o4[gid] = v;
    if (gid == 0 && has_loss)
        out[(size_t)BH_ * T_ * D_] = g_loss * (0.0001f / (float)((size_t)BH_ * T_ * D_));
}

// ---------------- launch ----------------
extern "C" void kernel_launch(void* const* d_in, const int* in_sizes, int n_in,
                              void* d_out, int out_size) {
    const float* qk    = (const float*)d_in[0];
    const float* v     = (const float*)d_in[1];
    const float* means = (const float*)d_in[2];
    const float* relw  = (const float*)d_in[3];
    if (n_in >= 4 && in_sizes[2] == W_ * H_ * D_ && in_sizes[3] == H_ * C_ * D_) {
        relw  = (const float*)d_in[2];
        means = (const float*)d_in[3];
    }
    float* out = (float*)d_out;

    cudaMemsetAsync(d_out, 0, (size_t)out_size * sizeof(float), 0);
    k_zero<<<(BH_ * T_ + 255) / 256, 256>>>();

    dim3 g1(T_ / 64, BH_);
    k_dists<<<g1, 256>>>(qk, means);

    k_topk<<<BH_ * C_, 512>>>();

    cudaFuncSetAttribute(k_attn, cudaFuncAttributeMaxDynamicSharedMemorySize, SMEM_ATTN_BYTES);
    k_attn<<<BH_ * C_, 512, SMEM_ATTN_BYTES>>>(qk, v, relw, out);

    int nf4 = BH_ * T_ * D_ / 4;
    k_norm<<<nf4 / 256, 256>>>(out, out_size > BH_ * T_ * D_ ? 1 : 0);
}

// round 7
// speedup vs baseline: 1.7243x; 1.0587x over previous
#include <cuda_runtime.h>
#include <cuda_bf16.h>
#include <cstdint>
#include <math.h>

#define B_ 4
#define H_ 8
#define T_ 8192
#define D_ 64
#define C_ 64
#define W_ 128
#define BH_ (B_*H_)

// ---------------- scratch ----------------
__device__ float g_dists[(size_t)BH_ * C_ * T_];   // [bh][c][t]
__device__ int   g_idx[BH_ * C_ * W_];
__device__ float g_den[BH_ * T_];
__device__ float g_loss;

__device__ __forceinline__ uint32_t packbf(__nv_bfloat16 a, __nv_bfloat16 b) {
    return ((uint32_t)__bfloat16_as_ushort(b) << 16) | (uint32_t)__bfloat16_as_ushort(a);
}
__device__ __forceinline__ void split2(float x, float y, uint32_t& hi, uint32_t& lo) {
    __nv_bfloat16 hx = __float2bfloat16_rn(x), hy = __float2bfloat16_rn(y);
    hi = packbf(hx, hy);
    lo = packbf(__float2bfloat16_rn(x - __bfloat162float(hx)),
                __float2bfloat16_rn(y - __bfloat162float(hy)));
}
__device__ __forceinline__ void mma_bf16(float (&c)[4], const uint32_t (&a)[4],
                                         uint32_t b0, uint32_t b1) {
    asm volatile("mma.sync.aligned.m16n8k16.row.col.f32.bf16.bf16.f32 "
        "{%0,%1,%2,%3}, {%4,%5,%6,%7}, {%8,%9}, {%0,%1,%2,%3};"
        : "+f"(c[0]), "+f"(c[1]), "+f"(c[2]), "+f"(c[3])
        : "r"(a[0]), "r"(a[1]), "r"(a[2]), "r"(a[3]), "r"(b0), "r"(b1));
}
__device__ __forceinline__ void ldsm4(uint32_t (&r)[4], uint32_t addr) {
    asm volatile("ldmatrix.sync.aligned.m8n8.x4.shared.b16 {%0,%1,%2,%3}, [%4];"
        : "=r"(r[0]), "=r"(r[1]), "=r"(r[2]), "=r"(r[3]) : "r"(addr));
}
__device__ __forceinline__ void ldsm4t(uint32_t (&r)[4], uint32_t addr) {
    asm volatile("ldmatrix.sync.aligned.m8n8.x4.trans.shared.b16 {%0,%1,%2,%3}, [%4];"
        : "=r"(r[0]), "=r"(r[1]), "=r"(r[2]), "=r"(r[3]) : "r"(addr));
}
__device__ __forceinline__ uint32_t smem_u32(const void* p) {
    uint32_t a;
    asm("{ .reg .u64 t; cvta.to.shared.u64 t, %1; cvt.u32.u64 %0, t; }" : "=r"(a) : "l"(p));
    return a;
}

// ---------------- zero den/loss ----------------
__global__ void k_zero() {
    int i = blockIdx.x * blockDim.x + threadIdx.x;
    if (i < BH_ * T_) g_den[i] = 0.f;
    if (i == 0) g_loss = 0.f;
}

// ---------------- dists = l2norm(qk) . means, fused commitment loss ----------------
__global__ void __launch_bounds__(256) k_dists(const float* __restrict__ qk,
                                               const float* __restrict__ means) {
    __shared__ float sQ[64 * 65];
    __shared__ float sM[64 * 65];
    __shared__ float sInv[64];
    int bh = blockIdx.y;
    int h = bh & (H_ - 1);
    int t0 = blockIdx.x * 64;
    const float* qp = qk + ((size_t)bh * T_ + t0) * D_;
    const float* mp = means + (size_t)h * C_ * D_;
    int tid = threadIdx.x;

    for (int i = tid; i < 64 * 16; i += 256) {
        int r = i >> 4, c4 = (i & 15) << 2;
        float4 a = *(const float4*)(qp + r * D_ + c4);
        sQ[r * 65 + c4 + 0] = a.x; sQ[r * 65 + c4 + 1] = a.y;
        sQ[r * 65 + c4 + 2] = a.z; sQ[r * 65 + c4 + 3] = a.w;
        float4 m = *(const float4*)(mp + r * D_ + c4);
        sM[r * 65 + c4 + 0] = m.x; sM[r * 65 + c4 + 1] = m.y;
        sM[r * 65 + c4 + 2] = m.z; sM[r * 65 + c4 + 3] = m.w;
    }
    __syncthreads();
    if (tid < 64) {
        float s = 0.f;
        #pragma unroll
        for (int k = 0; k < 64; k++) { float x = sQ[tid * 65 + k]; s += x * x; }
        sInv[tid] = 1.f / fmaxf(sqrtf(s), 1e-12f);
    }
    __syncthreads();

    int ty = tid >> 4, tx = tid & 15;
    float acc[4][4];
    #pragma unroll
    for (int u = 0; u < 4; u++)
        #pragma unroll
        for (int w = 0; w < 4; w++) acc[u][w] = 0.f;

    for (int k = 0; k < 64; k++) {
        float a[4], b[4];
        #pragma unroll
        for (int u = 0; u < 4; u++) a[u] = sQ[(ty * 4 + u) * 65 + k];
        #pragma unroll
        for (int w = 0; w < 4; w++) b[w] = sM[(tx * 4 + w) * 65 + k];
        #pragma unroll
        for (int u = 0; u < 4; u++)
            #pragma unroll
            for (int w = 0; w < 4; w++) acc[u][w] += a[u] * b[w];
    }
    __syncthreads();
    #pragma unroll
    for (int u = 0; u < 4; u++)
        #pragma unroll
        for (int w = 0; w < 4; w++)
            sQ[(tx * 4 + w) * 65 + (ty * 4 + u)] = acc[u][w] * sInv[ty * 4 + u];
    __syncthreads();
    float* dst = &g_dists[((size_t)bh * C_) * T_ + t0];
    for (int i = tid; i < 4096; i += 256) {
        int c = i >> 6, r = i & 63;
        dst[(size_t)c * T_ + r] = sQ[c * 65 + r];
    }
    if (tid < 64) {
        float m = -1e30f;
        #pragma unroll 8
        for (int c = 0; c < 64; c++) m = fmaxf(m, sQ[c * 65 + tid]);
        float v = 2.f - 2.f * m;
        #pragma unroll
        for (int off = 16; off > 0; off >>= 1) v += __shfl_down_sync(0xFFFFFFFFu, v, off);
        if ((tid & 31) == 0) atomicAdd(&g_loss, v);
    }
}

// ---------------- exact top-128 per (bh,c) row + ascending index sort ----------------
__global__ void __launch_bounds__(512) k_topk() {
    int row = blockIdx.x;
    const float* dp = g_dists + (size_t)row * T_;
    int tid = threadIdx.x;
    unsigned key[16];
    #pragma unroll
    for (int k = 0; k < 16; k++) {
        unsigned u = __float_as_uint(dp[tid + (k << 9)]);
        key[k] = (u & 0x80000000u) ? ~u : (u | 0x80000000u);
    }
    __shared__ int hist[256];
    __shared__ int sc[256];
    __shared__ int sSel, sKth, sCnt, sMin;
    __shared__ int sIdx[128];

    unsigned prefix = 0, pmask = 0;
    int kth = 128;
    for (int shift = 24; shift >= 0; shift -= 8) {
        if (tid < 256) hist[tid] = 0;
        __syncthreads();
        #pragma unroll
        for (int k = 0; k < 16; k++)
            if ((key[k] & pmask) == prefix)
                atomicAdd(&hist[(key[k] >> shift) & 255], 1);
        __syncthreads();
        // single-warp suffix scan: sc[b] = sum_{x>=b} hist[x]
        if (tid < 32) {
            int base = tid * 8;
            int v[8]; int s = 0;
            #pragma unroll
            for (int j = 0; j < 8; j++) { v[j] = hist[base + j]; s += v[j]; }
            int suf = s;
            #pragma unroll
            for (int off = 1; off < 32; off <<= 1) {
                int t = __shfl_down_sync(0xFFFFFFFFu, suf, off);
                if (tid + off < 32) suf += t;
            }
            int tail = suf - s;
            int run = 0;
            #pragma unroll
            for (int j = 7; j >= 0; j--) { run += v[j]; sc[base + j] = tail + run; }
        }
        __syncthreads();
        if (tid < 256) {
            int cum = sc[tid];
            int nxt = (tid < 255) ? sc[tid + 1] : 0;
            if (cum >= kth && nxt < kth) { sSel = tid; sKth = kth - nxt; }
        }
        __syncthreads();
        prefix |= ((unsigned)sSel) << shift;
        pmask  |= 0xFFu << shift;
        kth = sKth;
        __syncthreads();
    }
    if (tid == 0) sCnt = 0;
    __syncthreads();
    #pragma unroll
    for (int k = 0; k < 16; k++)
        if (key[k] > prefix) {
            int p = atomicAdd(&sCnt, 1);
            sIdx[p] = tid + (k << 9);
        }
    __syncthreads();
    int ngt = sCnt;
    int need = 128 - ngt;
    int last = -1;
    for (int s = 0; s < need; s++) {
        if (tid == 0) sMin = 0x7FFFFFFF;
        __syncthreads();
        #pragma unroll
        for (int k = 0; k < 16; k++) {
            if (key[k] == prefix) {
                int id2 = tid + (k << 9);
                if (id2 > last) atomicMin(&sMin, id2);
            }
        }
        __syncthreads();
        int m = sMin;
        if (tid == 0) sIdx[ngt + s] = m;
        last = m;
        __syncthreads();
    }
    for (int sz = 2; sz <= 128; sz <<= 1) {
        for (int st = sz >> 1; st > 0; st >>= 1) {
            if (tid < 128) {
                int i = tid, ixj = i ^ st;
                if (ixj > i) {
                    int a = sIdx[i], b2 = sIdx[ixj];
                    bool up = ((i & sz) == 0);
                    if ((a > b2) == up) { sIdx[i] = b2; sIdx[ixj] = a; }
                }
            }
            __syncthreads();
        }
    }
    if (tid < 128) g_idx[row * W_ + tid] = sIdx[tid];
}

// ---------------- fused gather + HMMA attention + scatter ----------------
// bf16 operand arrays [128][72]; fp32 sD [128][132] (row pitch 528B).
// After softmax, P is stored bf16 hi/lo INSIDE sD rows: hi @ row+0 (256B), lo @ row+256.
#define OFF_AHI   0u
#define OFF_ALO   18432u
#define OFF_R     36864u
#define OFF_VHI   55296u
#define OFF_VLO   73728u
#define OFF_D     92160u
#define OFF_INV   159744u
#define OFF_IDXS  160256u
#define SMEM_ATTN_BYTES 160768u

#define STR_BF 72
#define STR_D  132

__global__ void __launch_bounds__(512)
k_attn(const float* __restrict__ qk,
       const float* __restrict__ vv,
       const float* __restrict__ relw,
       float* __restrict__ outNum) {
    extern __shared__ char sm[];
    float* sD   = (float*)(sm + OFF_D);
    float* sInv = (float*)(sm + OFF_INV);
    int*   sIdx = (int*)(sm + OFF_IDXS);
    uint32_t sbase = smem_u32(sm);

    int bhc = blockIdx.x;
    int bh = bhc >> 6;
    int h = bh & (H_ - 1);
    int tid = threadIdx.x;

    if (tid < 128) sIdx[tid] = g_idx[bhc * W_ + tid];
    __syncthreads();

    // ---- fused gather: q->A hi/lo + norms; v->V hi/lo; rel->R ----
    for (int i = tid; i < 128 * 16; i += 512) {
        int r = i >> 4, c4 = (i & 15) << 2;
        int tok = sIdx[r];
        uint32_t off = (uint32_t)(r * STR_BF + c4) * 2;
        uint32_t hi0, lo0, hi1, lo1;

        float4 q4 = *(const float4*)(qk + ((size_t)bh * T_ + tok) * D_ + c4);
        split2(q4.x, q4.y, hi0, lo0);
        split2(q4.z, q4.w, hi1, lo1);
        *(uint32_t*)(sm + OFF_AHI + off)     = hi0;
        *(uint32_t*)(sm + OFF_AHI + off + 4) = hi1;
        *(uint32_t*)(sm + OFF_ALO + off)     = lo0;
        *(uint32_t*)(sm + OFF_ALO + off + 4) = lo1;
        float s = q4.x * q4.x + q4.y * q4.y + q4.z * q4.z + q4.w * q4.w;
        s += __shfl_xor_sync(0xFFFFFFFFu, s, 1);
        s += __shfl_xor_sync(0xFFFFFFFFu, s, 2);
        s += __shfl_xor_sync(0xFFFFFFFFu, s, 4);
        s += __shfl_xor_sync(0xFFFFFFFFu, s, 8);
        if ((tid & 15) == 0) sInv[r] = 1.f / fmaxf(sqrtf(s), 1e-12f);

        float4 v4 = *(const float4*)(vv + ((size_t)bh * T_ + tok) * D_ + c4);
        split2(v4.x, v4.y, hi0, lo0);
        split2(v4.z, v4.w, hi1, lo1);
        *(uint32_t*)(sm + OFF_VHI + off)     = hi0;
        *(uint32_t*)(sm + OFF_VHI + off + 4) = hi1;
        *(uint32_t*)(sm + OFF_VLO + off)     = lo0;
        *(uint32_t*)(sm + OFF_VLO + off + 4) = lo1;

        float4 r4 = *(const float4*)(relw + ((size_t)r * H_ + h) * D_ + c4);
        *(uint32_t*)(sm + OFF_R + off)     = packbf(__float2bfloat16_rn(r4.x), __float2bfloat16_rn(r4.y));
        *(uint32_t*)(sm + OFF_R + off + 4) = packbf(__float2bfloat16_rn(r4.z), __float2bfloat16_rn(r4.w));
    }
    __syncthreads();

    const int lane = tid & 31, warp = tid >> 5;
    const int qr = lane >> 2, qc = (lane & 3) << 1;
    const float scale = 0.125f;

    const int aKof = (lane >> 4) << 3;
    const int aRowL = lane & 15;
    const int bRowOf = ((lane >> 4) << 3) + (lane & 7);
    const int bKof = ((lane >> 3) & 1) << 3;

    // ---- GEMM1+2: warp = 32 rows x 32 cols (symmetry: B read from Q arrays) ----
    {
        const int R0 = (warp & 3) << 5;
        const int C0 = (warp >> 2) << 5;
        float acc[2][4][4], rac[2][4][4];
        #pragma unroll
        for (int rb = 0; rb < 2; rb++)
            #pragma unroll
            for (int nt = 0; nt < 4; nt++)
                #pragma unroll
                for (int u = 0; u < 4; u++) { acc[rb][nt][u] = 0.f; rac[rb][nt][u] = 0.f; }

        #pragma unroll
        for (int kt = 0; kt < 4; kt++) {
            int ka = kt * 16;
            uint32_t ah[2][4], al[2][4];
            #pragma unroll
            for (int rb = 0; rb < 2; rb++) {
                uint32_t aAddr = sbase + OFF_AHI + (uint32_t)((R0 + rb * 16 + aRowL) * STR_BF + ka + aKof) * 2;
                ldsm4(ah[rb], aAddr);
                ldsm4(al[rb], aAddr + (OFF_ALO - OFF_AHI));
            }
            #pragma unroll
            for (int p = 0; p < 2; p++) {
                uint32_t bAddr = sbase + OFF_AHI + (uint32_t)((C0 + p * 16 + bRowOf) * STR_BF + ka + bKof) * 2;
                uint32_t bhv[4], blv[4], brv[4];
                ldsm4(bhv, bAddr);
                ldsm4(blv, bAddr + (OFF_ALO - OFF_AHI));
                ldsm4(brv, bAddr + (OFF_R - OFF_AHI));
                #pragma unroll
                for (int rb = 0; rb < 2; rb++) {
                    mma_bf16(acc[rb][2 * p],     ah[rb], bhv[0], bhv[1]);
                    mma_bf16(acc[rb][2 * p],     ah[rb], blv[0], blv[1]);
                    mma_bf16(acc[rb][2 * p],     al[rb], bhv[0], bhv[1]);
                    mma_bf16(acc[rb][2 * p + 1], ah[rb], bhv[2], bhv[3]);
                    mma_bf16(acc[rb][2 * p + 1], ah[rb], blv[2], blv[3]);
                    mma_bf16(acc[rb][2 * p + 1], al[rb], bhv[2], bhv[3]);
                    mma_bf16(rac[rb][2 * p],     ah[rb], brv[0], brv[1]);
                    mma_bf16(rac[rb][2 * p + 1], ah[rb], brv[2], brv[3]);
                }
            }
        }
        // store dots, scaled by column inv-norm
        #pragma unroll
        for (int nt = 0; nt < 4; nt++) {
            int col = C0 + nt * 8 + qc;
            float i0v = sInv[col] * scale, i1v = sInv[col + 1] * scale;
            #pragma unroll
            for (int rb = 0; rb < 2; rb++) {
                int r0 = R0 + rb * 16 + qr;
                sD[r0 * STR_D + col]           = acc[rb][nt][0] * i0v;
                sD[r0 * STR_D + col + 1]       = acc[rb][nt][1] * i1v;
                sD[(r0 + 8) * STR_D + col]     = acc[rb][nt][2] * i0v;
                sD[(r0 + 8) * STR_D + col + 1] = acc[rb][nt][3] * i1v;
            }
        }
        __syncthreads();
        // shifted rel add
        #pragma unroll
        for (int nt = 0; nt < 4; nt++) {
            int jj = C0 + nt * 8 + qc;
            #pragma unroll
            for (int rb = 0; rb < 2; rb++) {
                int i0 = R0 + rb * 16 + qr;
                int j0 = i0 + jj - 127;
                if (j0 >= 0)                     sD[i0 * STR_D + j0]     += rac[rb][nt][0] * scale;
                if (j0 + 1 >= 0 && j0 + 1 <= i0) sD[i0 * STR_D + j0 + 1] += rac[rb][nt][1] * scale;
                int i1 = i0 + 8;
                int j1 = i1 + jj - 127;
                if (j1 >= 0)                     sD[i1 * STR_D + j1]     += rac[rb][nt][2] * scale;
                if (j1 + 1 >= 0 && j1 + 1 <= i1) sD[i1 * STR_D + j1 + 1] += rac[rb][nt][3] * scale;
            }
        }
    }
    __syncthreads();

    // ---- in-register softmax (4 threads/row) + direct P bf16 hi/lo store into sD rows ----
    {
        int r = tid >> 2, q4i = tid & 3;
        const float4* rp = (const float4*)(sD + r * STR_D + q4i * 32);
        int dcol = r - q4i * 32;
        float v[32];
        #pragma unroll
        for (int j4 = 0; j4 < 8; j4++) {
            float4 x = rp[j4];
            v[4 * j4 + 0] = (4 * j4 + 0 == dcol) ? -50000.0f : x.x;
            v[4 * j4 + 1] = (4 * j4 + 1 == dcol) ? -50000.0f : x.y;
            v[4 * j4 + 2] = (4 * j4 + 2 == dcol) ? -50000.0f : x.z;
            v[4 * j4 + 3] = (4 * j4 + 3 == dcol) ? -50000.0f : x.w;
        }
        float mx = -1e30f;
        #pragma unroll
        for (int j = 0; j < 32; j++) mx = fmaxf(mx, v[j]);
        mx = fmaxf(mx, __shfl_xor_sync(0xFFFFFFFFu, mx, 1));
        mx = fmaxf(mx, __shfl_xor_sync(0xFFFFFFFFu, mx, 2));
        float s = 0.f;
        #pragma unroll
        for (int j = 0; j < 32; j++) { v[j] = expf(v[j] - mx); s += v[j]; }
        s += __shfl_xor_sync(0xFFFFFFFFu, s, 1);
        s += __shfl_xor_sync(0xFFFFFFFFu, s, 2);
        float is = 1.f / s;
        __syncthreads();   // all fp32 reads done before bf16 overwrite
        char* rowb = sm + OFF_D + (uint32_t)r * 528u;
        #pragma unroll
        for (int t = 0; t < 16; t++) {
            uint32_t hi, lo;
            split2(v[2 * t] * is, v[2 * t + 1] * is, hi, lo);
            *(uint32_t*)(rowb + q4i * 64 + 4 * t)       = hi;
            *(uint32_t*)(rowb + 256 + q4i * 64 + 4 * t) = lo;
        }
    }
    __syncthreads();

    // ---- GEMM3: AV; A = P hi/lo from sD rows (pitch 528), B = V via ldsm.trans ----
    {
        const int R0g = (warp >> 1) << 4;
        const int chalf = warp & 1;
        float av[4][4];
        #pragma unroll
        for (int nt = 0; nt < 4; nt++)
            #pragma unroll
            for (int u = 0; u < 4; u++) av[nt][u] = 0.f;

        const int tKrow = ((lane >> 3) & 1) * 8 + (lane & 7);
        const int tDcol = ((lane >> 4) & 1) * 8;

        #pragma unroll
        for (int kt = 0; kt < 8; kt++) {
            int ka = kt * 16;
            uint32_t pAddr = sbase + OFF_D + (uint32_t)(R0g + aRowL) * 528u + (uint32_t)(ka + aKof) * 2;
            uint32_t ph[4], pl[4];
            ldsm4(ph, pAddr);
            ldsm4(pl, pAddr + 256);
            #pragma unroll
            for (int p = 0; p < 2; p++) {
                int n0 = chalf * 32 + p * 16;
                uint32_t vAddr = sbase + OFF_VHI + (uint32_t)((ka + tKrow) * STR_BF + n0 + tDcol) * 2;
                uint32_t vh[4], vl[4];
                ldsm4t(vh, vAddr);
                ldsm4t(vl, vAddr + (OFF_VLO - OFF_VHI));
                mma_bf16(av[2 * p],     ph, vh[0], vh[1]);
                mma_bf16(av[2 * p],     ph, vl[0], vl[1]);
                mma_bf16(av[2 * p],     pl, vh[0], vh[1]);
                mma_bf16(av[2 * p + 1], ph, vh[2], vh[3]);
                mma_bf16(av[2 * p + 1], ph, vl[2], vl[3]);
                mma_bf16(av[2 * p + 1], pl, vh[2], vh[3]);
            }
        }
        int tok0 = sIdx[R0g + qr];
        int tok1 = sIdx[R0g + qr + 8];
        float* op0 = outNum + ((size_t)bh * T_ + tok0) * D_;
        float* op1 = outNum + ((size_t)bh * T_ + tok1) * D_;
        #pragma unroll
        for (int nt = 0; nt < 4; nt++) {
            int col = chalf * 32 + nt * 8 + qc;
            atomicAdd((float2*)(op0 + col), make_float2(av[nt][0], av[nt][1]));
            atomicAdd((float2*)(op1 + col), make_float2(av[nt][2], av[nt][3]));
        }
    }
    if (tid < 128) atomicAdd(&g_den[(size_t)bh * T_ + sIdx[tid]], 1.0f);
}

// ---------------- normalize out = num/(den+eps); write loss ----------------
__global__ void k_norm(float* __restrict__ out, int has_loss) {
    size_t gid = (size_t)blockIdx.x * 256 + threadIdx.x;
    float den = g_den[gid >> 4];
    float s = 1.f / (den + 1e-5f);
    float4* o4 = (float4*)out;
    float4 v = o4[gid];
    v.x *= s; v.y *= s; v.z *= s; v.w *= s;
    o4[gid] = v;
    if (gid == 0 && has_loss)
        out[(size_t)BH_ * T_ * D_] = g_loss * (0.0001f / (float)((size_t)BH_ * T_ * D_));
}

// ---------------- launch ----------------
extern "C" void kernel_launch(void* const* d_in, const int* in_sizes, int n_in,
                              void* d_out, int out_size) {
    const float* qk    = (const float*)d_in[0];
    const float* v     = (const float*)d_in[1];
    const float* means = (const float*)d_in[2];
    const float* relw  = (const float*)d_in[3];
    if (n_in >= 4 && in_sizes[2] == W_ * H_ * D_ && in_sizes[3] == H_ * C_ * D_) {
        relw  = (const float*)d_in[2];
        means = (const float*)d_in[3];
    }
    float* out = (float*)d_out;

    cudaMemsetAsync(d_out, 0, (size_t)out_size * sizeof(float), 0);
    k_zero<<<(BH_ * T_ + 255) / 256, 256>>>();

    dim3 g1(T_ / 64, BH_);
    k_dists<<<g1, 256>>>(qk, means);

    k_topk<<<BH_ * C_, 512>>>();

    cudaFuncSetAttribute(k_attn, cudaFuncAttributeMaxDynamicSharedMemorySize, SMEM_ATTN_BYTES);
    k_attn<<<BH_ * C_, 512, SMEM_ATTN_BYTES>>>(qk, v, relw, out);

    int nf4 = BH_ * T_ * D_ / 4;
    k_norm<<<nf4 / 256, 256>>>(out, out_size > BH_ * T_ * D_ ? 1 : 0);
}